// round 4
// baseline (speedup 1.0000x reference)
#include <cuda_runtime.h>
#include <cuda_bf16.h>
#include <cstdint>

// Problem constants
#define B_  32
#define S_  512
#define D_  768
#define H_  12
#define HD_ 64
#define SCALE_ 0.125f
// SCALE * log2(e): scores computed directly in log2 domain
#define QSC 0.18033688011112042f

#define M_TOT (B_ * S_)          // 16384
#define QKV_N (3 * D_)           // 2304

__device__ float g_qkv[(size_t)M_TOT * QKV_N];   // [M, 3D]
__device__ float g_attn[(size_t)M_TOT * D_];     // [M, D]

// ---------------------------------------------------------------------------
// Helpers
// ---------------------------------------------------------------------------
__device__ __forceinline__ uint32_t f2tf32(float x) {
    uint32_t r;
    asm("cvt.rna.tf32.f32 %0, %1;" : "=r"(r) : "f"(x));
    return r;
}

__device__ __forceinline__ void mma_tf32(float d[4], const uint32_t a[4],
                                         const uint32_t b[2]) {
    asm volatile(
        "mma.sync.aligned.m16n8k8.row.col.f32.tf32.tf32.f32 "
        "{%0,%1,%2,%3},{%4,%5,%6,%7},{%8,%9},{%0,%1,%2,%3};\n"
        : "+f"(d[0]), "+f"(d[1]), "+f"(d[2]), "+f"(d[3])
        : "r"(a[0]), "r"(a[1]), "r"(a[2]), "r"(a[3]),
          "r"(b[0]), "r"(b[1]));
}

// ldmatrix x4 over 8x4 tiles of 32-bit elements (b16 form).
__device__ __forceinline__ void ldsm4(uint32_t r[4], uint32_t saddr) {
    asm volatile(
        "ldmatrix.sync.aligned.m8n8.x4.shared.b16 {%0,%1,%2,%3},[%4];"
        : "=r"(r[0]), "=r"(r[1]), "=r"(r[2]), "=r"(r[3])
        : "r"(saddr));
}

__device__ __forceinline__ uint32_t smem_u32(const void* p) {
    return (uint32_t)__cvta_generic_to_shared(p);
}

// 2^t on the FMA pipe only.
__device__ __forceinline__ float exp2_poly(float t) {
    float g  = t + 12582912.0f;
    int   j  = __float_as_int(g);
    float nf = g - 12582912.0f;
    float f  = t - nf;
    float p  = 0.0096181f;
    p = fmaf(p, f, 0.0555041f);
    p = fmaf(p, f, 0.2402265f);
    p = fmaf(p, f, 0.6931472f);
    p = fmaf(p, f, 1.0f);
    int n = j - 0x4B400000;
    return __int_as_float(__float_as_int(p) + (n << 23));
}

// ---------------------------------------------------------------------------
// TF32 tensor-core GEMM, double-buffered, ldmatrix fragment feed.
// C[M,N] = A[M,K] @ B[N,K]^T + bias[N]
// BM=BN=128, BK=16, 256 threads = 8 warps (2x4), warp tile 64x32.
// ---------------------------------------------------------------------------
#define BM 128
#define BN 128
#define BK 16
#define SKEW 4
#define LDA (BK + SKEW)    // 20 words (== 4 mod 32 -> ldmatrix conflict-free)

__global__ __launch_bounds__(256, 2) void gemm_tc_kernel(
    const float* __restrict__ A, const float* __restrict__ Bw,
    const float* __restrict__ bias, float* __restrict__ C,
    int M, int N, int K)
{
    __shared__ uint32_t As[2][BM][LDA];
    __shared__ uint32_t Bs[2][BN][LDA];

    const int tid  = threadIdx.x;
    const int lane = tid & 31;
    const int warp = tid >> 5;
    const int wm   = warp >> 2;
    const int wn   = warp & 3;
    const int m0   = blockIdx.y * BM;
    const int n0   = blockIdx.x * BN;

    const int lrow0 = tid >> 2;
    const int lrow1 = lrow0 + 64;
    const int lkq   = (tid & 3) << 2;

    const float* Aptr = A  + (size_t)(m0 + lrow0) * K + lkq;
    const float* Bptr = Bw + (size_t)(n0 + lrow0) * K + lkq;

    float acc[4][4][4];
    #pragma unroll
    for (int mi = 0; mi < 4; mi++)
        #pragma unroll
        for (int ni = 0; ni < 4; ni++)
            #pragma unroll
            for (int r = 0; r < 4; r++) acc[mi][ni][r] = 0.0f;

    const int nk = K / BK;
    float4 areg0, areg1, breg0, breg1;

    areg0 = *(const float4*)(Aptr);
    areg1 = *(const float4*)(Aptr + (size_t)64 * K);
    breg0 = *(const float4*)(Bptr);
    breg1 = *(const float4*)(Bptr + (size_t)64 * K);
    *(uint4*)&As[0][lrow0][lkq] = make_uint4(f2tf32(areg0.x), f2tf32(areg0.y),
                                             f2tf32(areg0.z), f2tf32(areg0.w));
    *(uint4*)&As[0][lrow1][lkq] = make_uint4(f2tf32(areg1.x), f2tf32(areg1.y),
                                             f2tf32(areg1.z), f2tf32(areg1.w));
    *(uint4*)&Bs[0][lrow0][lkq] = make_uint4(f2tf32(breg0.x), f2tf32(breg0.y),
                                             f2tf32(breg0.z), f2tf32(breg0.w));
    *(uint4*)&Bs[0][lrow1][lkq] = make_uint4(f2tf32(breg1.x), f2tf32(breg1.y),
                                             f2tf32(breg1.z), f2tf32(breg1.w));
    __syncthreads();

    // ldmatrix lane decomposition: mat = lane>>3, row = lane&7
    const int l_row  = lane & 7;
    const int sel_a  = (lane >> 3) & 1;   // A: +8 rows      B: +4 k
    const int sel_b  = (lane >> 4) & 1;   // A: +4 k         B: +8 rows (ni hi)
    const int arow   = wm * 64 + l_row + 8 * sel_a;
    const int acol   = 4 * sel_b;
    const int brow   = wn * 32 + l_row + 8 * sel_b;
    const int bcol   = 4 * sel_a;

    for (int kt = 0; kt < nk; kt++) {
        const int cur = kt & 1;
        const bool more = (kt + 1 < nk);
        if (more) {
            const float* An = Aptr + (size_t)(kt + 1) * BK;
            const float* Bn = Bptr + (size_t)(kt + 1) * BK;
            areg0 = *(const float4*)(An);
            areg1 = *(const float4*)(An + (size_t)64 * K);
            breg0 = *(const float4*)(Bn);
            breg1 = *(const float4*)(Bn + (size_t)64 * K);
        }

        #pragma unroll
        for (int ks = 0; ks < BK; ks += 8) {
            uint32_t afr[4][4];
            #pragma unroll
            for (int mi = 0; mi < 4; mi++)
                ldsm4(afr[mi], smem_u32(&As[cur][arow + mi * 16][ks + acol]));
            uint32_t bfr[2][4];
            #pragma unroll
            for (int p = 0; p < 2; p++)
                ldsm4(bfr[p], smem_u32(&Bs[cur][brow + p * 16][ks + bcol]));
            #pragma unroll
            for (int mi = 0; mi < 4; mi++)
                #pragma unroll
                for (int p = 0; p < 2; p++) {
                    mma_tf32(acc[mi][2 * p],     afr[mi], &bfr[p][0]);
                    mma_tf32(acc[mi][2 * p + 1], afr[mi], &bfr[p][2]);
                }
        }

        if (more) {
            const int nxt = cur ^ 1;
            *(uint4*)&As[nxt][lrow0][lkq] = make_uint4(f2tf32(areg0.x), f2tf32(areg0.y),
                                                       f2tf32(areg0.z), f2tf32(areg0.w));
            *(uint4*)&As[nxt][lrow1][lkq] = make_uint4(f2tf32(areg1.x), f2tf32(areg1.y),
                                                       f2tf32(areg1.z), f2tf32(areg1.w));
            *(uint4*)&Bs[nxt][lrow0][lkq] = make_uint4(f2tf32(breg0.x), f2tf32(breg0.y),
                                                       f2tf32(breg0.z), f2tf32(breg0.w));
            *(uint4*)&Bs[nxt][lrow1][lkq] = make_uint4(f2tf32(breg1.x), f2tf32(breg1.y),
                                                       f2tf32(breg1.z), f2tf32(breg1.w));
        }
        __syncthreads();
    }

    const int rlo = lane >> 2;
    const int rc  = lane & 3;
    #pragma unroll
    for (int ni = 0; ni < 4; ni++) {
        int col = n0 + wn * 32 + ni * 8 + rc * 2;
        float2 bv = *(const float2*)(bias + col);
        #pragma unroll
        for (int mi = 0; mi < 4; mi++) {
            int row = m0 + wm * 64 + mi * 16 + rlo;
            float2 o0, o1;
            o0.x = acc[mi][ni][0] + bv.x;
            o0.y = acc[mi][ni][1] + bv.y;
            o1.x = acc[mi][ni][2] + bv.x;
            o1.y = acc[mi][ni][3] + bv.y;
            *(float2*)(C + (size_t)row * N + col)       = o0;
            *(float2*)(C + (size_t)(row + 8) * N + col) = o1;
        }
    }
}

// ---------------------------------------------------------------------------
// TF32 tensor-core flash attention with ldmatrix fragment feed (Q, K, P).
// Block = (b, h, 64-row q tile); 128 threads = 4 warps, warp owns 16 q rows.
// smem strides: Qs/Ks/Ps 68 (== 4 mod 32, ldmatrix conflict-free), Vs 72.
// ---------------------------------------------------------------------------
#define AT_FLOATS (3 * 64 * 68 + 64 * 72)
#define AT_BYTES  (AT_FLOATS * 4)

__global__ __launch_bounds__(128) void attn_tc_kernel(
    const float* __restrict__ qkv, float* __restrict__ out)
{
    const int bid = blockIdx.x;
    const int qt  = bid & 7;
    const int h   = (bid >> 3) % H_;
    const int b   = bid / (H_ * 8);

    const int tid  = threadIdx.x;
    const int lane = tid & 31;
    const int warp = tid >> 5;
    const int qr   = lane >> 2;
    const int qc   = lane & 3;
    const int R    = warp * 16;

    extern __shared__ uint32_t smu[];
    uint32_t* Qs = smu;                 // [64][68]
    uint32_t* Ks = smu + 64 * 68;       // [64][68]
    uint32_t* Ps = smu + 2 * 64 * 68;   // [64][68]
    uint32_t* Vs = smu + 3 * 64 * 68;   // [64][72]

    // ldmatrix decomposition
    const int l_row = lane & 7;
    const int s_a   = (lane >> 3) & 1;
    const int s_b   = (lane >> 4) & 1;
    // A-side (Q / P): rows (+8 on s_a), k (+4 on s_b)
    const int aro = l_row + 8 * s_a;
    const int aco = 4 * s_b;
    // B-side (K): rows nt (+8 on s_b), k (+4 on s_a)
    const int bro = l_row + 8 * s_b;
    const int bco = 4 * s_a;

    const float* qbase = qkv + (size_t)(b * S_ + qt * 64) * QKV_N + h * HD_;

    for (int t = tid; t < 1024; t += 128) {
        int r  = t >> 4;
        int c4 = (t & 15) << 2;
        float4 v = *(const float4*)(qbase + (size_t)r * QKV_N + c4);
        *(uint4*)&Qs[r * 68 + c4] =
            make_uint4(f2tf32(v.x * QSC), f2tf32(v.y * QSC),
                       f2tf32(v.z * QSC), f2tf32(v.w * QSC));
    }

    float m1 = -1e30f, m2 = -1e30f, l1 = 0.0f, l2 = 0.0f;
    float o[8][4];
    #pragma unroll
    for (int nt = 0; nt < 8; nt++)
        #pragma unroll
        for (int r = 0; r < 4; r++) o[nt][r] = 0.0f;

    for (int kt = 0; kt < 8; kt++) {
        const float* kbase = qkv + (size_t)(b * S_ + kt * 64) * QKV_N + D_ + h * HD_;
        const float* vbase = kbase + D_;

        __syncthreads();
        for (int t = tid; t < 1024; t += 128) {
            int r  = t >> 4;
            int c4 = (t & 15) << 2;
            float4 kk = *(const float4*)(kbase + (size_t)r * QKV_N + c4);
            *(uint4*)&Ks[r * 68 + c4] =
                make_uint4(f2tf32(kk.x), f2tf32(kk.y), f2tf32(kk.z), f2tf32(kk.w));
            float4 vv = *(const float4*)(vbase + (size_t)r * QKV_N + c4);
            *(uint4*)&Vs[r * 72 + c4] =
                make_uint4(f2tf32(vv.x), f2tf32(vv.y), f2tf32(vv.z), f2tf32(vv.w));
        }
        __syncthreads();

        // S = Q K^T (log2 domain)
        float s[8][4];
        #pragma unroll
        for (int nt = 0; nt < 8; nt++)
            #pragma unroll
            for (int r = 0; r < 4; r++) s[nt][r] = 0.0f;

        #pragma unroll
        for (int k8 = 0; k8 < HD_; k8 += 8) {
            uint32_t a[4];
            ldsm4(a, smem_u32(&Qs[(R + aro) * 68 + k8 + aco]));
            #pragma unroll
            for (int p = 0; p < 4; p++) {
                uint32_t bb[4];
                ldsm4(bb, smem_u32(&Ks[(p * 16 + bro) * 68 + k8 + bco]));
                mma_tf32(s[2 * p],     a, &bb[0]);
                mma_tf32(s[2 * p + 1], a, &bb[2]);
            }
        }

        // Online softmax (base-2)
        float mx1 = -1e30f, mx2 = -1e30f;
        #pragma unroll
        for (int nt = 0; nt < 8; nt++) {
            mx1 = fmaxf(mx1, fmaxf(s[nt][0], s[nt][1]));
            mx2 = fmaxf(mx2, fmaxf(s[nt][2], s[nt][3]));
        }
        mx1 = fmaxf(mx1, __shfl_xor_sync(0xffffffffu, mx1, 1));
        mx1 = fmaxf(mx1, __shfl_xor_sync(0xffffffffu, mx1, 2));
        mx2 = fmaxf(mx2, __shfl_xor_sync(0xffffffffu, mx2, 1));
        mx2 = fmaxf(mx2, __shfl_xor_sync(0xffffffffu, mx2, 2));

        float mn1 = fmaxf(m1, mx1);
        float mn2 = fmaxf(m2, mx2);
        float c1 = exp2f(m1 - mn1);
        float c2 = exp2f(m2 - mn2);
        m1 = mn1; m2 = mn2;

        float rs1 = 0.0f, rs2 = 0.0f;
        #pragma unroll
        for (int nt = 0; nt < 8; nt++) {
            s[nt][0] = exp2_poly(s[nt][0] - mn1);
            s[nt][1] = exp2_poly(s[nt][1] - mn1);
            s[nt][2] = exp2_poly(s[nt][2] - mn2);
            s[nt][3] = exp2_poly(s[nt][3] - mn2);
            rs1 += s[nt][0] + s[nt][1];
            rs2 += s[nt][2] + s[nt][3];
        }
        rs1 += __shfl_xor_sync(0xffffffffu, rs1, 1);
        rs1 += __shfl_xor_sync(0xffffffffu, rs1, 2);
        rs2 += __shfl_xor_sync(0xffffffffu, rs2, 1);
        rs2 += __shfl_xor_sync(0xffffffffu, rs2, 2);
        l1 = l1 * c1 + rs1;
        l2 = l2 * c2 + rs2;

        #pragma unroll
        for (int nt = 0; nt < 8; nt++) {
            o[nt][0] *= c1; o[nt][1] *= c1;
            o[nt][2] *= c2; o[nt][3] *= c2;
        }

        // Stage P (tf32) into warp-private Ps rows
        #pragma unroll
        for (int nt = 0; nt < 8; nt++) {
            *(uint2*)&Ps[(R + qr) * 68 + nt * 8 + 2 * qc] =
                make_uint2(f2tf32(s[nt][0]), f2tf32(s[nt][1]));
            *(uint2*)&Ps[(R + qr + 8) * 68 + nt * 8 + 2 * qc] =
                make_uint2(f2tf32(s[nt][2]), f2tf32(s[nt][3]));
        }
        __syncwarp();

        // O += P @ V   (P via ldmatrix, V scalar: conflict-free pattern)
        #pragma unroll
        for (int k8 = 0; k8 < 64; k8 += 8) {
            uint32_t a[4];
            ldsm4(a, smem_u32(&Ps[(R + aro) * 68 + k8 + aco]));
            #pragma unroll
            for (int nt = 0; nt < 8; nt++) {
                uint32_t bb[2];
                bb[0] = Vs[(k8 + qc) * 72 + nt * 8 + qr];
                bb[1] = Vs[(k8 + qc + 4) * 72 + nt * 8 + qr];
                mma_tf32(o[nt], a, bb);
            }
        }
        __syncwarp();
    }

    float i1 = 1.0f / l1;
    float i2 = 1.0f / l2;
    float* ob = out + (size_t)(b * S_ + qt * 64) * D_ + h * HD_;
    #pragma unroll
    for (int nt = 0; nt < 8; nt++) {
        int col = nt * 8 + 2 * qc;
        *(float2*)(ob + (size_t)(R + qr) * D_ + col) =
            make_float2(o[nt][0] * i1, o[nt][1] * i1);
        *(float2*)(ob + (size_t)(R + qr + 8) * D_ + col) =
            make_float2(o[nt][2] * i2, o[nt][3] * i2);
    }
}

// ---------------------------------------------------------------------------
// Launch
// ---------------------------------------------------------------------------
extern "C" void kernel_launch(void* const* d_in, const int* in_sizes, int n_in,
                              void* d_out, int out_size)
{
    const float* x      = (const float*)d_in[0];
    const float* qkv_w  = (const float*)d_in[1];
    const float* qkv_b  = (const float*)d_in[2];
    const float* proj_w = (const float*)d_in[3];
    const float* proj_b = (const float*)d_in[4];
    float* out = (float*)d_out;

    void* qkv_ptr = nullptr;
    void* attn_ptr = nullptr;
    cudaGetSymbolAddress(&qkv_ptr, g_qkv);
    cudaGetSymbolAddress(&attn_ptr, g_attn);
    float* qkv_s  = (float*)qkv_ptr;
    float* attn_s = (float*)attn_ptr;

    cudaFuncSetAttribute(attn_tc_kernel,
                         cudaFuncAttributeMaxDynamicSharedMemorySize,
                         AT_BYTES);

    gemm_tc_kernel<<<dim3(QKV_N / BN, M_TOT / BM), 256>>>(
        x, qkv_w, qkv_b, qkv_s, M_TOT, QKV_N, D_);

    attn_tc_kernel<<<B_ * H_ * (S_ / 64), 128, AT_BYTES>>>(qkv_s, attn_s);

    gemm_tc_kernel<<<dim3(D_ / BN, M_TOT / BM), 256>>>(
        attn_s, proj_w, proj_b, out, M_TOT, D_, D_);
}

// round 7
// speedup vs baseline: 1.3085x; 1.3085x over previous
#include <cuda_runtime.h>
#include <cuda_bf16.h>
#include <cstdint>

// Problem constants
#define B_  32
#define S_  512
#define D_  768
#define H_  12
#define HD_ 64
#define SCALE_ 0.125f
// SCALE * log2(e): scores computed directly in log2 domain
#define QSC 0.18033688011112042f

#define M_TOT (B_ * S_)          // 16384
#define QKV_N (3 * D_)           // 2304

__device__ float g_qkv[(size_t)M_TOT * QKV_N];   // [M, 3D]
__device__ float g_attn[(size_t)M_TOT * D_];     // [M, D]

// ---------------------------------------------------------------------------
// Helpers
// ---------------------------------------------------------------------------
__device__ __forceinline__ uint32_t f2tf32(float x) {
    uint32_t r;
    asm("cvt.rna.tf32.f32 %0, %1;" : "=r"(r) : "f"(x));
    return r;
}

__device__ __forceinline__ void mma_tf32(float d[4], const uint32_t a[4],
                                         const uint32_t b[2]) {
    asm volatile(
        "mma.sync.aligned.m16n8k8.row.col.f32.tf32.tf32.f32 "
        "{%0,%1,%2,%3},{%4,%5,%6,%7},{%8,%9},{%0,%1,%2,%3};\n"
        : "+f"(d[0]), "+f"(d[1]), "+f"(d[2]), "+f"(d[3])
        : "r"(a[0]), "r"(a[1]), "r"(a[2]), "r"(a[3]),
          "r"(b[0]), "r"(b[1]));
}

// 2^t on the FMA pipe only.
__device__ __forceinline__ float exp2_poly(float t) {
    float g  = t + 12582912.0f;
    int   j  = __float_as_int(g);
    float nf = g - 12582912.0f;
    float f  = t - nf;
    float p  = 0.0096181f;
    p = fmaf(p, f, 0.0555041f);
    p = fmaf(p, f, 0.2402265f);
    p = fmaf(p, f, 0.6931472f);
    p = fmaf(p, f, 1.0f);
    int n = j - 0x4B400000;
    return __int_as_float(__float_as_int(p) + (n << 23));
}

// ---------------------------------------------------------------------------
// TF32 tensor-core GEMM, 64x64 warp tiles.
// C[M,N] = A[M,K] @ B[N,K]^T + bias[N]
// BM=128, BN=256, BK=16. 256 threads = 8 warps (2x4), warp tile 64x64.
// Double-buffered dynamic smem, register-staged global prefetch,
// scalar conflict-free LDS fragment feed (stride 20).
// ---------------------------------------------------------------------------
#define BM 128
#define BN 256
#define BK 16
#define LDW 20                       // BK + 4 skew words
#define A_WORDS (BM * LDW)           // per buffer
#define B_WORDS (BN * LDW)
#define GEMM_SMEM_BYTES (2 * (A_WORDS + B_WORDS) * 4)   // 61440

__global__ __launch_bounds__(256) void gemm_tc_kernel(
    const float* __restrict__ A, const float* __restrict__ Bw,
    const float* __restrict__ bias, float* __restrict__ C,
    int M, int N, int K)
{
    extern __shared__ uint32_t gsm[];
    uint32_t* As = gsm;                        // [2][BM][LDW]
    uint32_t* Bs = gsm + 2 * A_WORDS;          // [2][BN][LDW]

    const int tid  = threadIdx.x;
    const int lane = tid & 31;
    const int warp = tid >> 5;
    const int wm   = warp >> 2;        // 0..1 : 64-row half
    const int wn   = warp & 3;         // 0..3 : 64-col quarter
    const int m0   = blockIdx.y * BM;
    const int n0   = blockIdx.x * BN;

    // loader mapping: f = i*256 + tid; row = f>>2; kq = (f&3)*4
    const int lrow = tid >> 2;          // 0..63
    const int lkq  = (tid & 3) << 2;

    const float* Aptr = A  + (size_t)(m0 + lrow) * K + lkq;
    const float* Bptr = Bw + (size_t)(n0 + lrow) * K + lkq;

    float acc[4][8][4];
    #pragma unroll
    for (int mi = 0; mi < 4; mi++)
        #pragma unroll
        for (int ni = 0; ni < 8; ni++)
            #pragma unroll
            for (int r = 0; r < 4; r++) acc[mi][ni][r] = 0.0f;

    const int nk = K / BK;
    float4 ar[2], br[4];

    // prefetch chunk 0
    #pragma unroll
    for (int i = 0; i < 2; i++)
        ar[i] = *(const float4*)(Aptr + (size_t)(i * 64) * K);
    #pragma unroll
    for (int i = 0; i < 4; i++)
        br[i] = *(const float4*)(Bptr + (size_t)(i * 64) * K);

    // store chunk 0 -> buf 0
    #pragma unroll
    for (int i = 0; i < 2; i++)
        *(uint4*)&As[(lrow + i * 64) * LDW + lkq] =
            make_uint4(f2tf32(ar[i].x), f2tf32(ar[i].y),
                       f2tf32(ar[i].z), f2tf32(ar[i].w));
    #pragma unroll
    for (int i = 0; i < 4; i++)
        *(uint4*)&Bs[(lrow + i * 64) * LDW + lkq] =
            make_uint4(f2tf32(br[i].x), f2tf32(br[i].y),
                       f2tf32(br[i].z), f2tf32(br[i].w));
    __syncthreads();

    const int qr = lane >> 2;      // 0..7
    const int qc = lane & 3;       // 0..3

    for (int kt = 0; kt < nk; kt++) {
        const int cur = kt & 1;
        const bool more = (kt + 1 < nk);
        if (more) {
            const float* An = Aptr + (size_t)(kt + 1) * BK;
            const float* Bn = Bptr + (size_t)(kt + 1) * BK;
            #pragma unroll
            for (int i = 0; i < 2; i++)
                ar[i] = *(const float4*)(An + (size_t)(i * 64) * K);
            #pragma unroll
            for (int i = 0; i < 4; i++)
                br[i] = *(const float4*)(Bn + (size_t)(i * 64) * K);
        }

        const uint32_t* Ab = As + cur * A_WORDS;
        const uint32_t* Bb = Bs + cur * B_WORDS;

        #pragma unroll
        for (int ks = 0; ks < BK; ks += 8) {
            uint32_t afr[4][4];
            #pragma unroll
            for (int mi = 0; mi < 4; mi++) {
                int rb = (wm * 64 + mi * 16 + qr) * LDW + ks + qc;
                afr[mi][0] = Ab[rb];
                afr[mi][1] = Ab[rb + 8 * LDW];
                afr[mi][2] = Ab[rb + 4];
                afr[mi][3] = Ab[rb + 8 * LDW + 4];
            }
            uint32_t bfr[8][2];
            #pragma unroll
            for (int ni = 0; ni < 8; ni++) {
                int cb = (wn * 64 + ni * 8 + qr) * LDW + ks + qc;
                bfr[ni][0] = Bb[cb];
                bfr[ni][1] = Bb[cb + 4];
            }
            #pragma unroll
            for (int mi = 0; mi < 4; mi++)
                #pragma unroll
                for (int ni = 0; ni < 8; ni++)
                    mma_tf32(acc[mi][ni], afr[mi], bfr[ni]);
        }

        if (more) {
            const int nxt = cur ^ 1;
            uint32_t* Aw = As + nxt * A_WORDS;
            uint32_t* Bn2 = Bs + nxt * B_WORDS;
            #pragma unroll
            for (int i = 0; i < 2; i++)
                *(uint4*)&Aw[(lrow + i * 64) * LDW + lkq] =
                    make_uint4(f2tf32(ar[i].x), f2tf32(ar[i].y),
                               f2tf32(ar[i].z), f2tf32(ar[i].w));
            #pragma unroll
            for (int i = 0; i < 4; i++)
                *(uint4*)&Bn2[(lrow + i * 64) * LDW + lkq] =
                    make_uint4(f2tf32(br[i].x), f2tf32(br[i].y),
                               f2tf32(br[i].z), f2tf32(br[i].w));
        }
        __syncthreads();
    }

    // Epilogue: bias + store
    #pragma unroll
    for (int ni = 0; ni < 8; ni++) {
        int col = n0 + wn * 64 + ni * 8 + qc * 2;
        float2 bv = *(const float2*)(bias + col);
        #pragma unroll
        for (int mi = 0; mi < 4; mi++) {
            int row = m0 + wm * 64 + mi * 16 + qr;
            float2 o0, o1;
            o0.x = acc[mi][ni][0] + bv.x;
            o0.y = acc[mi][ni][1] + bv.y;
            o1.x = acc[mi][ni][2] + bv.x;
            o1.y = acc[mi][ni][3] + bv.y;
            *(float2*)(C + (size_t)row * N + col)       = o0;
            *(float2*)(C + (size_t)(row + 8) * N + col) = o1;
        }
    }
}

// ---------------------------------------------------------------------------
// TF32 mma.sync flash attention (round-3 version — best known).
// Block = (b, h, 64-row q tile); 128 threads = 4 warps, warp owns 16 q rows.
// ---------------------------------------------------------------------------
#define AT_FLOATS (3 * 64 * 68 + 64 * 72)
#define AT_BYTES  (AT_FLOATS * 4)

__global__ __launch_bounds__(128) void attn_tc_kernel(
    const float* __restrict__ qkv, float* __restrict__ out)
{
    const int bid = blockIdx.x;
    const int qt  = bid & 7;
    const int h   = (bid >> 3) % H_;
    const int b   = bid / (H_ * 8);

    const int tid  = threadIdx.x;
    const int lane = tid & 31;
    const int warp = tid >> 5;
    const int qr   = lane >> 2;
    const int qc   = lane & 3;
    const int R    = warp * 16;

    extern __shared__ uint32_t smu[];
    uint32_t* Qs = smu;                 // [64][68]
    uint32_t* Ks = smu + 64 * 68;       // [64][68]
    uint32_t* Ps = smu + 2 * 64 * 68;   // [64][68]
    uint32_t* Vs = smu + 3 * 64 * 68;   // [64][72]

    const float* qbase = qkv + (size_t)(b * S_ + qt * 64) * QKV_N + h * HD_;

    for (int t = tid; t < 1024; t += 128) {
        int r  = t >> 4;
        int c4 = (t & 15) << 2;
        float4 v = *(const float4*)(qbase + (size_t)r * QKV_N + c4);
        *(uint4*)&Qs[r * 68 + c4] =
            make_uint4(f2tf32(v.x * QSC), f2tf32(v.y * QSC),
                       f2tf32(v.z * QSC), f2tf32(v.w * QSC));
    }

    float m1 = -1e30f, m2 = -1e30f, l1 = 0.0f, l2 = 0.0f;
    float o[8][4];
    #pragma unroll
    for (int nt = 0; nt < 8; nt++)
        #pragma unroll
        for (int r = 0; r < 4; r++) o[nt][r] = 0.0f;

    for (int kt = 0; kt < 8; kt++) {
        const float* kbase = qkv + (size_t)(b * S_ + kt * 64) * QKV_N + D_ + h * HD_;
        const float* vbase = kbase + D_;

        __syncthreads();
        for (int t = tid; t < 1024; t += 128) {
            int r  = t >> 4;
            int c4 = (t & 15) << 2;
            float4 kk = *(const float4*)(kbase + (size_t)r * QKV_N + c4);
            *(uint4*)&Ks[r * 68 + c4] =
                make_uint4(f2tf32(kk.x), f2tf32(kk.y), f2tf32(kk.z), f2tf32(kk.w));
            float4 vv = *(const float4*)(vbase + (size_t)r * QKV_N + c4);
            *(uint4*)&Vs[r * 72 + c4] =
                make_uint4(f2tf32(vv.x), f2tf32(vv.y), f2tf32(vv.z), f2tf32(vv.w));
        }
        __syncthreads();

        float s[8][4];
        #pragma unroll
        for (int nt = 0; nt < 8; nt++)
            #pragma unroll
            for (int r = 0; r < 4; r++) s[nt][r] = 0.0f;

        #pragma unroll
        for (int k8 = 0; k8 < HD_; k8 += 8) {
            uint32_t a[4];
            a[0] = Qs[(R + qr) * 68 + k8 + qc];
            a[1] = Qs[(R + qr + 8) * 68 + k8 + qc];
            a[2] = Qs[(R + qr) * 68 + k8 + qc + 4];
            a[3] = Qs[(R + qr + 8) * 68 + k8 + qc + 4];
            #pragma unroll
            for (int nt = 0; nt < 8; nt++) {
                uint32_t bb[2];
                bb[0] = Ks[(nt * 8 + qr) * 68 + k8 + qc];
                bb[1] = Ks[(nt * 8 + qr) * 68 + k8 + qc + 4];
                mma_tf32(s[nt], a, bb);
            }
        }

        float mx1 = -1e30f, mx2 = -1e30f;
        #pragma unroll
        for (int nt = 0; nt < 8; nt++) {
            mx1 = fmaxf(mx1, fmaxf(s[nt][0], s[nt][1]));
            mx2 = fmaxf(mx2, fmaxf(s[nt][2], s[nt][3]));
        }
        mx1 = fmaxf(mx1, __shfl_xor_sync(0xffffffffu, mx1, 1));
        mx1 = fmaxf(mx1, __shfl_xor_sync(0xffffffffu, mx1, 2));
        mx2 = fmaxf(mx2, __shfl_xor_sync(0xffffffffu, mx2, 1));
        mx2 = fmaxf(mx2, __shfl_xor_sync(0xffffffffu, mx2, 2));

        float mn1 = fmaxf(m1, mx1);
        float mn2 = fmaxf(m2, mx2);
        float c1 = exp2f(m1 - mn1);
        float c2 = exp2f(m2 - mn2);
        m1 = mn1; m2 = mn2;

        float rs1 = 0.0f, rs2 = 0.0f;
        #pragma unroll
        for (int nt = 0; nt < 8; nt++) {
            s[nt][0] = exp2_poly(s[nt][0] - mn1);
            s[nt][1] = exp2_poly(s[nt][1] - mn1);
            s[nt][2] = exp2_poly(s[nt][2] - mn2);
            s[nt][3] = exp2_poly(s[nt][3] - mn2);
            rs1 += s[nt][0] + s[nt][1];
            rs2 += s[nt][2] + s[nt][3];
        }
        rs1 += __shfl_xor_sync(0xffffffffu, rs1, 1);
        rs1 += __shfl_xor_sync(0xffffffffu, rs1, 2);
        rs2 += __shfl_xor_sync(0xffffffffu, rs2, 1);
        rs2 += __shfl_xor_sync(0xffffffffu, rs2, 2);
        l1 = l1 * c1 + rs1;
        l2 = l2 * c2 + rs2;

        #pragma unroll
        for (int nt = 0; nt < 8; nt++) {
            o[nt][0] *= c1; o[nt][1] *= c1;
            o[nt][2] *= c2; o[nt][3] *= c2;
        }

        #pragma unroll
        for (int nt = 0; nt < 8; nt++) {
            *(uint2*)&Ps[(R + qr) * 68 + nt * 8 + 2 * qc] =
                make_uint2(f2tf32(s[nt][0]), f2tf32(s[nt][1]));
            *(uint2*)&Ps[(R + qr + 8) * 68 + nt * 8 + 2 * qc] =
                make_uint2(f2tf32(s[nt][2]), f2tf32(s[nt][3]));
        }
        __syncwarp();

        #pragma unroll
        for (int k8 = 0; k8 < 64; k8 += 8) {
            uint32_t a[4];
            a[0] = Ps[(R + qr) * 68 + k8 + qc];
            a[1] = Ps[(R + qr + 8) * 68 + k8 + qc];
            a[2] = Ps[(R + qr) * 68 + k8 + qc + 4];
            a[3] = Ps[(R + qr + 8) * 68 + k8 + qc + 4];
            #pragma unroll
            for (int nt = 0; nt < 8; nt++) {
                uint32_t bb[2];
                bb[0] = Vs[(k8 + qc) * 72 + nt * 8 + qr];
                bb[1] = Vs[(k8 + qc + 4) * 72 + nt * 8 + qr];
                mma_tf32(o[nt], a, bb);
            }
        }
        __syncwarp();
    }

    float i1 = 1.0f / l1;
    float i2 = 1.0f / l2;
    float* ob = out + (size_t)(b * S_ + qt * 64) * D_ + h * HD_;
    #pragma unroll
    for (int nt = 0; nt < 8; nt++) {
        int col = nt * 8 + 2 * qc;
        *(float2*)(ob + (size_t)(R + qr) * D_ + col) =
            make_float2(o[nt][0] * i1, o[nt][1] * i1);
        *(float2*)(ob + (size_t)(R + qr + 8) * D_ + col) =
            make_float2(o[nt][2] * i2, o[nt][3] * i2);
    }
}

// ---------------------------------------------------------------------------
// Launch
// ---------------------------------------------------------------------------
extern "C" void kernel_launch(void* const* d_in, const int* in_sizes, int n_in,
                              void* d_out, int out_size)
{
    const float* x      = (const float*)d_in[0];
    const float* qkv_w  = (const float*)d_in[1];
    const float* qkv_b  = (const float*)d_in[2];
    const float* proj_w = (const float*)d_in[3];
    const float* proj_b = (const float*)d_in[4];
    float* out = (float*)d_out;

    void* qkv_ptr = nullptr;
    void* attn_ptr = nullptr;
    cudaGetSymbolAddress(&qkv_ptr, g_qkv);
    cudaGetSymbolAddress(&attn_ptr, g_attn);
    float* qkv_s  = (float*)qkv_ptr;
    float* attn_s = (float*)attn_ptr;

    cudaFuncSetAttribute(gemm_tc_kernel,
                         cudaFuncAttributeMaxDynamicSharedMemorySize,
                         GEMM_SMEM_BYTES);
    cudaFuncSetAttribute(attn_tc_kernel,
                         cudaFuncAttributeMaxDynamicSharedMemorySize,
                         AT_BYTES);

    // 1) QKV projection: [16384,768] @ [2304,768]^T + b
    gemm_tc_kernel<<<dim3(QKV_N / BN, M_TOT / BM), 256, GEMM_SMEM_BYTES>>>(
        x, qkv_w, qkv_b, qkv_s, M_TOT, QKV_N, D_);

    // 2) Flash attention
    attn_tc_kernel<<<B_ * H_ * (S_ / 64), 128, AT_BYTES>>>(qkv_s, attn_s);

    // 3) Output projection: [16384,768] @ [768,768]^T + b
    gemm_tc_kernel<<<dim3(D_ / BN, M_TOT / BM), 256, GEMM_SMEM_BYTES>>>(
        attn_s, proj_w, proj_b, out, M_TOT, D_, D_);
}

// round 9
// speedup vs baseline: 1.3488x; 1.0308x over previous
#include <cuda_runtime.h>
#include <cuda_bf16.h>
#include <cstdint>

// Problem constants
#define B_  32
#define S_  512
#define D_  768
#define H_  12
#define HD_ 64
#define SCALE_ 0.125f
// SCALE * log2(e): scores computed directly in log2 domain
#define QSC 0.18033688011112042f

#define M_TOT (B_ * S_)          // 16384
#define QKV_N (3 * D_)           // 2304

// Scratch (device globals — allocation-free)
__device__ float g_qkv[(size_t)M_TOT * QKV_N];   // [M, 3D] raw f32 QKV
__device__ float g_attn[(size_t)M_TOT * D_];     // [M, D] attn out (tf32-rounded)
__device__ float g_xt[(size_t)M_TOT * D_];       // x pre-converted to tf32
__device__ float g_qkvw[(size_t)QKV_N * D_];     // qkv_w pre-converted
__device__ float g_projw[(size_t)D_ * D_];       // proj_w pre-converted

// ---------------------------------------------------------------------------
// Helpers
// ---------------------------------------------------------------------------
__device__ __forceinline__ uint32_t f2tf32(float x) {
    uint32_t r;
    asm("cvt.rna.tf32.f32 %0, %1;" : "=r"(r) : "f"(x));
    return r;
}

__device__ __forceinline__ void mma_tf32(float d[4], const uint32_t a[4],
                                         const uint32_t b[2]) {
    asm volatile(
        "mma.sync.aligned.m16n8k8.row.col.f32.tf32.tf32.f32 "
        "{%0,%1,%2,%3},{%4,%5,%6,%7},{%8,%9},{%0,%1,%2,%3};\n"
        : "+f"(d[0]), "+f"(d[1]), "+f"(d[2]), "+f"(d[3])
        : "r"(a[0]), "r"(a[1]), "r"(a[2]), "r"(a[3]),
          "r"(b[0]), "r"(b[1]));
}

__device__ __forceinline__ void cp_async16(uint32_t saddr, const void* gptr) {
    asm volatile("cp.async.cg.shared.global [%0], [%1], 16;"
                 :: "r"(saddr), "l"(gptr));
}
__device__ __forceinline__ void cp_commit() {
    asm volatile("cp.async.commit_group;");
}
template <int N>
__device__ __forceinline__ void cp_wait() {
    asm volatile("cp.async.wait_group %0;" :: "n"(N));
}

// 2^t on the FMA pipe only.
__device__ __forceinline__ float exp2_poly(float t) {
    float g  = t + 12582912.0f;
    int   j  = __float_as_int(g);
    float nf = g - 12582912.0f;
    float f  = t - nf;
    float p  = 0.0096181f;
    p = fmaf(p, f, 0.0555041f);
    p = fmaf(p, f, 0.2402265f);
    p = fmaf(p, f, 0.6931472f);
    p = fmaf(p, f, 1.0f);
    int n = j - 0x4B400000;
    return __int_as_float(__float_as_int(p) + (n << 23));
}

// ---------------------------------------------------------------------------
// Elementwise tf32 pre-convert (cvt.rna) pass.
// ---------------------------------------------------------------------------
__global__ void cvt_tf32_kernel(const float* __restrict__ in,
                                float* __restrict__ out, int n4)
{
    int i = blockIdx.x * blockDim.x + threadIdx.x;
    int step = gridDim.x * blockDim.x;
    for (; i < n4; i += step) {
        float4 v = *(const float4*)(in + (size_t)i * 4);
        uint4 o = make_uint4(f2tf32(v.x), f2tf32(v.y), f2tf32(v.z), f2tf32(v.w));
        *(uint4*)(out + (size_t)i * 4) = o;
    }
}

// ---------------------------------------------------------------------------
// TF32 tensor-core GEMM with 4-stage cp.async pipeline.
// C[M,N] = A[M,K] @ B[N,K]^T + bias[N]   (A, B already tf32-valued in gmem)
// BM=BN=128, BK=16. 256 threads = 8 warps (2x4), warp tile 64x32.
// ---------------------------------------------------------------------------
#define BM 128
#define BN 128
#define BK 16
#define LDW 20                        // BK + 4 skew words
#define STAGES 4
#define A_WORDS (BM * LDW)            // 2560 words per stage
#define STG_WORDS ((BM + BN) * LDW)   // 5120 words per stage
#define GEMM_SMEM_BYTES (STAGES * STG_WORDS * 4)   // 81920

__global__ __launch_bounds__(256) void gemm_tc_kernel(
    const float* __restrict__ A, const float* __restrict__ Bw,
    const float* __restrict__ bias, float* __restrict__ C,
    int M, int N, int K)
{
    extern __shared__ uint32_t gsm[];

    const int tid  = threadIdx.x;
    const int lane = tid & 31;
    const int warp = tid >> 5;
    const int wm   = warp >> 2;
    const int wn   = warp & 3;
    const int m0   = blockIdx.y * BM;
    const int n0   = blockIdx.x * BN;

    // loader mapping: row = tid>>2 (0..63, +64), col quad lkq = (tid&3)*4
    const int lrow = tid >> 2;
    const int lkq  = (tid & 3) << 2;

    const float* Aptr = A  + (size_t)(m0 + lrow) * K + lkq;
    const float* Bptr = Bw + (size_t)(n0 + lrow) * K + lkq;

    const uint32_t smem_base = (uint32_t)__cvta_generic_to_shared(gsm);
    // per-thread smem store offsets (bytes) within a stage
    const uint32_t a_off0 = ((lrow)      * LDW + lkq) * 4;
    const uint32_t a_off1 = ((lrow + 64) * LDW + lkq) * 4;
    const uint32_t b_off0 = (A_WORDS + (lrow)      * LDW + lkq) * 4;
    const uint32_t b_off1 = (A_WORDS + (lrow + 64) * LDW + lkq) * 4;

    const int nk = K / BK;

    float acc[4][4][4];
    #pragma unroll
    for (int mi = 0; mi < 4; mi++)
        #pragma unroll
        for (int ni = 0; ni < 4; ni++)
            #pragma unroll
            for (int r = 0; r < 4; r++) acc[mi][ni][r] = 0.0f;

    // Prologue: issue stages 0..STAGES-2
    #pragma unroll
    for (int s = 0; s < STAGES - 1; s++) {
        uint32_t sb = smem_base + s * STG_WORDS * 4;
        const float* Ak = Aptr + (size_t)s * BK;
        const float* Bk = Bptr + (size_t)s * BK;
        cp_async16(sb + a_off0, Ak);
        cp_async16(sb + a_off1, Ak + (size_t)64 * K);
        cp_async16(sb + b_off0, Bk);
        cp_async16(sb + b_off1, Bk + (size_t)64 * K);
        cp_commit();
    }

    const int qr = lane >> 2;
    const int qc = lane & 3;

    for (int kt = 0; kt < nk; kt++) {
        cp_wait<STAGES - 2>();
        __syncthreads();

        // issue stage kt+STAGES-1 (buffer (kt-1)%STAGES — safe after the sync)
        if (kt + STAGES - 1 < nk) {
            int s = (kt + STAGES - 1) & (STAGES - 1);
            uint32_t sb = smem_base + s * STG_WORDS * 4;
            const float* Ak = Aptr + (size_t)(kt + STAGES - 1) * BK;
            const float* Bk = Bptr + (size_t)(kt + STAGES - 1) * BK;
            cp_async16(sb + a_off0, Ak);
            cp_async16(sb + a_off1, Ak + (size_t)64 * K);
            cp_async16(sb + b_off0, Bk);
            cp_async16(sb + b_off1, Bk + (size_t)64 * K);
        }
        cp_commit();

        const uint32_t* Ab = gsm + (kt & (STAGES - 1)) * STG_WORDS;
        const uint32_t* Bb = Ab + A_WORDS;

        #pragma unroll
        for (int ks = 0; ks < BK; ks += 8) {
            uint32_t afr[4][4];
            #pragma unroll
            for (int mi = 0; mi < 4; mi++) {
                int rb = (wm * 64 + mi * 16 + qr) * LDW + ks + qc;
                afr[mi][0] = Ab[rb];
                afr[mi][1] = Ab[rb + 8 * LDW];
                afr[mi][2] = Ab[rb + 4];
                afr[mi][3] = Ab[rb + 8 * LDW + 4];
            }
            uint32_t bfr[4][2];
            #pragma unroll
            for (int ni = 0; ni < 4; ni++) {
                int cb = (wn * 32 + ni * 8 + qr) * LDW + ks + qc;
                bfr[ni][0] = Bb[cb];
                bfr[ni][1] = Bb[cb + 4];
            }
            #pragma unroll
            for (int mi = 0; mi < 4; mi++)
                #pragma unroll
                for (int ni = 0; ni < 4; ni++)
                    mma_tf32(acc[mi][ni], afr[mi], bfr[ni]);
        }
    }

    // Epilogue: bias + store
    #pragma unroll
    for (int ni = 0; ni < 4; ni++) {
        int col = n0 + wn * 32 + ni * 8 + qc * 2;
        float2 bv = *(const float2*)(bias + col);
        #pragma unroll
        for (int mi = 0; mi < 4; mi++) {
            int row = m0 + wm * 64 + mi * 16 + qr;
            float2 o0, o1;
            o0.x = acc[mi][ni][0] + bv.x;
            o0.y = acc[mi][ni][1] + bv.y;
            o1.x = acc[mi][ni][2] + bv.x;
            o1.y = acc[mi][ni][3] + bv.y;
            *(float2*)(C + (size_t)row * N + col)       = o0;
            *(float2*)(C + (size_t)(row + 8) * N + col) = o1;
        }
    }
}

// ---------------------------------------------------------------------------
// TF32 mma.sync flash attention (round-3 version; output stores tf32-rounded
// values so the proj GEMM can consume them via cp.async without conversion).
// ---------------------------------------------------------------------------
#define AT_FLOATS (3 * 64 * 68 + 64 * 72)
#define AT_BYTES  (AT_FLOATS * 4)

__global__ __launch_bounds__(128) void attn_tc_kernel(
    const float* __restrict__ qkv, float* __restrict__ out)
{
    const int bid = blockIdx.x;
    const int qt  = bid & 7;
    const int h   = (bid >> 3) % H_;
    const int b   = bid / (H_ * 8);

    const int tid  = threadIdx.x;
    const int lane = tid & 31;
    const int warp = tid >> 5;
    const int qr   = lane >> 2;
    const int qc   = lane & 3;
    const int R    = warp * 16;

    extern __shared__ uint32_t smu[];
    uint32_t* Qs = smu;                 // [64][68]
    uint32_t* Ks = smu + 64 * 68;       // [64][68]
    uint32_t* Ps = smu + 2 * 64 * 68;   // [64][68]
    uint32_t* Vs = smu + 3 * 64 * 68;   // [64][72]

    const float* qbase = qkv + (size_t)(b * S_ + qt * 64) * QKV_N + h * HD_;

    for (int t = tid; t < 1024; t += 128) {
        int r  = t >> 4;
        int c4 = (t & 15) << 2;
        float4 v = *(const float4*)(qbase + (size_t)r * QKV_N + c4);
        *(uint4*)&Qs[r * 68 + c4] =
            make_uint4(f2tf32(v.x * QSC), f2tf32(v.y * QSC),
                       f2tf32(v.z * QSC), f2tf32(v.w * QSC));
    }

    float m1 = -1e30f, m2 = -1e30f, l1 = 0.0f, l2 = 0.0f;
    float o[8][4];
    #pragma unroll
    for (int nt = 0; nt < 8; nt++)
        #pragma unroll
        for (int r = 0; r < 4; r++) o[nt][r] = 0.0f;

    for (int kt = 0; kt < 8; kt++) {
        const float* kbase = qkv + (size_t)(b * S_ + kt * 64) * QKV_N + D_ + h * HD_;
        const float* vbase = kbase + D_;

        __syncthreads();
        for (int t = tid; t < 1024; t += 128) {
            int r  = t >> 4;
            int c4 = (t & 15) << 2;
            float4 kk = *(const float4*)(kbase + (size_t)r * QKV_N + c4);
            *(uint4*)&Ks[r * 68 + c4] =
                make_uint4(f2tf32(kk.x), f2tf32(kk.y), f2tf32(kk.z), f2tf32(kk.w));
            float4 vv = *(const float4*)(vbase + (size_t)r * QKV_N + c4);
            *(uint4*)&Vs[r * 72 + c4] =
                make_uint4(f2tf32(vv.x), f2tf32(vv.y), f2tf32(vv.z), f2tf32(vv.w));
        }
        __syncthreads();

        float s[8][4];
        #pragma unroll
        for (int nt = 0; nt < 8; nt++)
            #pragma unroll
            for (int r = 0; r < 4; r++) s[nt][r] = 0.0f;

        #pragma unroll
        for (int k8 = 0; k8 < HD_; k8 += 8) {
            uint32_t a[4];
            a[0] = Qs[(R + qr) * 68 + k8 + qc];
            a[1] = Qs[(R + qr + 8) * 68 + k8 + qc];
            a[2] = Qs[(R + qr) * 68 + k8 + qc + 4];
            a[3] = Qs[(R + qr + 8) * 68 + k8 + qc + 4];
            #pragma unroll
            for (int nt = 0; nt < 8; nt++) {
                uint32_t bb[2];
                bb[0] = Ks[(nt * 8 + qr) * 68 + k8 + qc];
                bb[1] = Ks[(nt * 8 + qr) * 68 + k8 + qc + 4];
                mma_tf32(s[nt], a, bb);
            }
        }

        float mx1 = -1e30f, mx2 = -1e30f;
        #pragma unroll
        for (int nt = 0; nt < 8; nt++) {
            mx1 = fmaxf(mx1, fmaxf(s[nt][0], s[nt][1]));
            mx2 = fmaxf(mx2, fmaxf(s[nt][2], s[nt][3]));
        }
        mx1 = fmaxf(mx1, __shfl_xor_sync(0xffffffffu, mx1, 1));
        mx1 = fmaxf(mx1, __shfl_xor_sync(0xffffffffu, mx1, 2));
        mx2 = fmaxf(mx2, __shfl_xor_sync(0xffffffffu, mx2, 1));
        mx2 = fmaxf(mx2, __shfl_xor_sync(0xffffffffu, mx2, 2));

        float mn1 = fmaxf(m1, mx1);
        float mn2 = fmaxf(m2, mx2);
        float c1 = exp2f(m1 - mn1);
        float c2 = exp2f(m2 - mn2);
        m1 = mn1; m2 = mn2;

        float rs1 = 0.0f, rs2 = 0.0f;
        #pragma unroll
        for (int nt = 0; nt < 8; nt++) {
            s[nt][0] = exp2_poly(s[nt][0] - mn1);
            s[nt][1] = exp2_poly(s[nt][1] - mn1);
            s[nt][2] = exp2_poly(s[nt][2] - mn2);
            s[nt][3] = exp2_poly(s[nt][3] - mn2);
            rs1 += s[nt][0] + s[nt][1];
            rs2 += s[nt][2] + s[nt][3];
        }
        rs1 += __shfl_xor_sync(0xffffffffu, rs1, 1);
        rs1 += __shfl_xor_sync(0xffffffffu, rs1, 2);
        rs2 += __shfl_xor_sync(0xffffffffu, rs2, 1);
        rs2 += __shfl_xor_sync(0xffffffffu, rs2, 2);
        l1 = l1 * c1 + rs1;
        l2 = l2 * c2 + rs2;

        #pragma unroll
        for (int nt = 0; nt < 8; nt++) {
            o[nt][0] *= c1; o[nt][1] *= c1;
            o[nt][2] *= c2; o[nt][3] *= c2;
        }

        #pragma unroll
        for (int nt = 0; nt < 8; nt++) {
            *(uint2*)&Ps[(R + qr) * 68 + nt * 8 + 2 * qc] =
                make_uint2(f2tf32(s[nt][0]), f2tf32(s[nt][1]));
            *(uint2*)&Ps[(R + qr + 8) * 68 + nt * 8 + 2 * qc] =
                make_uint2(f2tf32(s[nt][2]), f2tf32(s[nt][3]));
        }
        __syncwarp();

        #pragma unroll
        for (int k8 = 0; k8 < 64; k8 += 8) {
            uint32_t a[4];
            a[0] = Ps[(R + qr) * 68 + k8 + qc];
            a[1] = Ps[(R + qr + 8) * 68 + k8 + qc];
            a[2] = Ps[(R + qr) * 68 + k8 + qc + 4];
            a[3] = Ps[(R + qr + 8) * 68 + k8 + qc + 4];
            #pragma unroll
            for (int nt = 0; nt < 8; nt++) {
                uint32_t bb[2];
                bb[0] = Vs[(k8 + qc) * 72 + nt * 8 + qr];
                bb[1] = Vs[(k8 + qc + 4) * 72 + nt * 8 + qr];
                mma_tf32(o[nt], a, bb);
            }
        }
        __syncwarp();
    }

    // Normalize + store tf32-rounded (consumed only by proj GEMM)
    float i1 = 1.0f / l1;
    float i2 = 1.0f / l2;
    float* ob = out + (size_t)(b * S_ + qt * 64) * D_ + h * HD_;
    #pragma unroll
    for (int nt = 0; nt < 8; nt++) {
        int col = nt * 8 + 2 * qc;
        uint2 w0 = make_uint2(f2tf32(o[nt][0] * i1), f2tf32(o[nt][1] * i1));
        uint2 w1 = make_uint2(f2tf32(o[nt][2] * i2), f2tf32(o[nt][3] * i2));
        *(uint2*)(ob + (size_t)(R + qr) * D_ + col)     = w0;
        *(uint2*)(ob + (size_t)(R + qr + 8) * D_ + col) = w1;
    }
}

// ---------------------------------------------------------------------------
// Launch
// ---------------------------------------------------------------------------
extern "C" void kernel_launch(void* const* d_in, const int* in_sizes, int n_in,
                              void* d_out, int out_size)
{
    const float* x      = (const float*)d_in[0];
    const float* qkv_w  = (const float*)d_in[1];
    const float* qkv_b  = (const float*)d_in[2];
    const float* proj_w = (const float*)d_in[3];
    const float* proj_b = (const float*)d_in[4];
    float* out = (float*)d_out;

    void *qkv_p, *attn_p, *xt_p, *qkvw_p, *projw_p;
    cudaGetSymbolAddress(&qkv_p, g_qkv);
    cudaGetSymbolAddress(&attn_p, g_attn);
    cudaGetSymbolAddress(&xt_p, g_xt);
    cudaGetSymbolAddress(&qkvw_p, g_qkvw);
    cudaGetSymbolAddress(&projw_p, g_projw);
    float* qkv_s   = (float*)qkv_p;
    float* attn_s  = (float*)attn_p;
    float* xt_s    = (float*)xt_p;
    float* qkvw_s  = (float*)qkvw_p;
    float* projw_s = (float*)projw_p;

    cudaFuncSetAttribute(gemm_tc_kernel,
                         cudaFuncAttributeMaxDynamicSharedMemorySize,
                         GEMM_SMEM_BYTES);
    cudaFuncSetAttribute(attn_tc_kernel,
                         cudaFuncAttributeMaxDynamicSharedMemorySize,
                         AT_BYTES);

    // 0) Pre-convert inputs to tf32 (cvt.rna) so GEMMs can cp.async raw bytes
    cvt_tf32_kernel<<<1024, 256>>>(x, xt_s, M_TOT * D_ / 4);
    cvt_tf32_kernel<<<512, 256>>>(qkv_w, qkvw_s, QKV_N * D_ / 4);
    cvt_tf32_kernel<<<256, 256>>>(proj_w, projw_s, D_ * D_ / 4);

    // 1) QKV projection: [16384,768] @ [2304,768]^T + b
    gemm_tc_kernel<<<dim3(QKV_N / BN, M_TOT / BM), 256, GEMM_SMEM_BYTES>>>(
        xt_s, qkvw_s, qkv_b, qkv_s, M_TOT, QKV_N, D_);

    // 2) Flash attention (stores tf32-rounded output)
    attn_tc_kernel<<<B_ * H_ * (S_ / 64), 128, AT_BYTES>>>(qkv_s, attn_s);

    // 3) Output projection: [16384,768] @ [768,768]^T + b
    gemm_tc_kernel<<<dim3(D_ / BN, M_TOT / BM), 256, GEMM_SMEM_BYTES>>>(
        attn_s, projw_s, proj_b, out, M_TOT, D_, D_);
}

// round 10
// speedup vs baseline: 1.9804x; 1.4683x over previous
#include <cuda_runtime.h>
#include <cuda_fp16.h>
#include <cstdint>

// Problem constants
#define B_  32
#define S_  512
#define D_  768
#define H_  12
#define HD_ 64
#define SCALE_ 0.125f
// SCALE * log2(e): scores computed directly in log2 domain
#define QSC 0.18033688011112042f

#define M_TOT (B_ * S_)          // 16384
#define QKV_N (3 * D_)           // 2304

// Scratch (device globals — allocation-free)
__device__ float  g_qkv[(size_t)M_TOT * QKV_N];    // [M, 3D] f32 QKV (GEMM1 out)
__device__ __half g_attnh[(size_t)M_TOT * D_];     // [M, D] attn out (fp16)
__device__ __half g_xh[(size_t)M_TOT * D_];        // x as fp16
__device__ __half g_qkvwh[(size_t)QKV_N * D_];     // qkv_w as fp16
__device__ __half g_projwh[(size_t)D_ * D_];       // proj_w as fp16

// ---------------------------------------------------------------------------
// Helpers
// ---------------------------------------------------------------------------
__device__ __forceinline__ uint32_t f2tf32(float x) {
    uint32_t r;
    asm("cvt.rna.tf32.f32 %0, %1;" : "=r"(r) : "f"(x));
    return r;
}

__device__ __forceinline__ void mma_tf32(float d[4], const uint32_t a[4],
                                         const uint32_t b[2]) {
    asm volatile(
        "mma.sync.aligned.m16n8k8.row.col.f32.tf32.tf32.f32 "
        "{%0,%1,%2,%3},{%4,%5,%6,%7},{%8,%9},{%0,%1,%2,%3};\n"
        : "+f"(d[0]), "+f"(d[1]), "+f"(d[2]), "+f"(d[3])
        : "r"(a[0]), "r"(a[1]), "r"(a[2]), "r"(a[3]),
          "r"(b[0]), "r"(b[1]));
}

__device__ __forceinline__ void mma_f16(float d[4], const uint32_t a[4],
                                        const uint32_t b[2]) {
    asm volatile(
        "mma.sync.aligned.m16n8k16.row.col.f32.f16.f16.f32 "
        "{%0,%1,%2,%3},{%4,%5,%6,%7},{%8,%9},{%0,%1,%2,%3};\n"
        : "+f"(d[0]), "+f"(d[1]), "+f"(d[2]), "+f"(d[3])
        : "r"(a[0]), "r"(a[1]), "r"(a[2]), "r"(a[3]),
          "r"(b[0]), "r"(b[1]));
}

__device__ __forceinline__ void cp_async16(uint32_t saddr, const void* gptr) {
    asm volatile("cp.async.cg.shared.global [%0], [%1], 16;"
                 :: "r"(saddr), "l"(gptr));
}
__device__ __forceinline__ void cp_commit() {
    asm volatile("cp.async.commit_group;");
}
template <int N>
__device__ __forceinline__ void cp_wait() {
    asm volatile("cp.async.wait_group %0;" :: "n"(N));
}

// 2^t on the FMA pipe only.
__device__ __forceinline__ float exp2_poly(float t) {
    float g  = t + 12582912.0f;
    int   j  = __float_as_int(g);
    float nf = g - 12582912.0f;
    float f  = t - nf;
    float p  = 0.0096181f;
    p = fmaf(p, f, 0.0555041f);
    p = fmaf(p, f, 0.2402265f);
    p = fmaf(p, f, 0.6931472f);
    p = fmaf(p, f, 1.0f);
    int n = j - 0x4B400000;
    return __int_as_float(__float_as_int(p) + (n << 23));
}

// ---------------------------------------------------------------------------
// Elementwise f32 -> fp16 (rn) pre-convert pass. Processes 8 elems/iter.
// ---------------------------------------------------------------------------
__global__ void cvt_f16_kernel(const float* __restrict__ in,
                               __half* __restrict__ out, int n8)
{
    int i = blockIdx.x * blockDim.x + threadIdx.x;
    int step = gridDim.x * blockDim.x;
    for (; i < n8; i += step) {
        float4 v0 = *(const float4*)(in + (size_t)i * 8);
        float4 v1 = *(const float4*)(in + (size_t)i * 8 + 4);
        __half2 h0 = __floats2half2_rn(v0.x, v0.y);
        __half2 h1 = __floats2half2_rn(v0.z, v0.w);
        __half2 h2 = __floats2half2_rn(v1.x, v1.y);
        __half2 h3 = __floats2half2_rn(v1.z, v1.w);
        uint4 o;
        o.x = *(uint32_t*)&h0; o.y = *(uint32_t*)&h1;
        o.z = *(uint32_t*)&h2; o.w = *(uint32_t*)&h3;
        *(uint4*)(out + (size_t)i * 8) = o;
    }
}

// ---------------------------------------------------------------------------
// FP16 tensor-core GEMM with 4-stage cp.async pipeline.
// C[M,N] = A[M,K] @ B[N,K]^T + bias[N]   (A, B fp16 in gmem, C f32)
// BM=BN=128, BK=32 halfs. 256 threads = 8 warps (2x4), warp tile 64x32.
// smem rows: 16 half2-words + 4 skew = 20 words (conflict-free feed).
// ---------------------------------------------------------------------------
#define BM 128
#define BN 128
#define BKH 32                        // K elems (halfs) per stage
#define LDW 20                        // 16 data words + 4 skew
#define STAGES 4
#define A_WORDS (BM * LDW)            // 2560 words per stage
#define STG_WORDS ((BM + BN) * LDW)   // 5120 words per stage
#define GEMM_SMEM_BYTES (STAGES * STG_WORDS * 4)   // 81920

__global__ __launch_bounds__(256) void gemm_f16_kernel(
    const __half* __restrict__ A, const __half* __restrict__ Bw,
    const float* __restrict__ bias, float* __restrict__ C,
    int M, int N, int K)
{
    extern __shared__ uint32_t gsm[];

    const int tid  = threadIdx.x;
    const int lane = tid & 31;
    const int warp = tid >> 5;
    const int wm   = warp >> 2;
    const int wn   = warp & 3;
    const int m0   = blockIdx.y * BM;
    const int n0   = blockIdx.x * BN;

    // loader: f = i*256 + tid (i<2 per matrix); row = f>>2; q = f&3
    // each transfer: 16B = 8 halfs at k-offset q*8, smem word offset q*4
    const int lrow = tid >> 2;          // 0..63
    const int lq   = tid & 3;

    const __half* Aptr = A  + (size_t)(m0 + lrow) * K + lq * 8;
    const __half* Bptr = Bw + (size_t)(n0 + lrow) * K + lq * 8;

    const uint32_t smem_base = (uint32_t)__cvta_generic_to_shared(gsm);
    const uint32_t a_off0 = ((lrow)      * LDW + lq * 4) * 4;
    const uint32_t a_off1 = ((lrow + 64) * LDW + lq * 4) * 4;
    const uint32_t b_off0 = (A_WORDS + (lrow)      * LDW + lq * 4) * 4;
    const uint32_t b_off1 = (A_WORDS + (lrow + 64) * LDW + lq * 4) * 4;

    const int nk = K / BKH;           // 24

    float acc[4][4][4];
    #pragma unroll
    for (int mi = 0; mi < 4; mi++)
        #pragma unroll
        for (int ni = 0; ni < 4; ni++)
            #pragma unroll
            for (int r = 0; r < 4; r++) acc[mi][ni][r] = 0.0f;

    // Prologue: stages 0..STAGES-2
    #pragma unroll
    for (int s = 0; s < STAGES - 1; s++) {
        uint32_t sb = smem_base + s * STG_WORDS * 4;
        const __half* Ak = Aptr + (size_t)s * BKH;
        const __half* Bk = Bptr + (size_t)s * BKH;
        cp_async16(sb + a_off0, Ak);
        cp_async16(sb + a_off1, Ak + (size_t)64 * K);
        cp_async16(sb + b_off0, Bk);
        cp_async16(sb + b_off1, Bk + (size_t)64 * K);
        cp_commit();
    }

    const int qr = lane >> 2;
    const int qc = lane & 3;

    for (int kt = 0; kt < nk; kt++) {
        cp_wait<STAGES - 2>();
        __syncthreads();

        if (kt + STAGES - 1 < nk) {
            int s = (kt + STAGES - 1) & (STAGES - 1);
            uint32_t sb = smem_base + s * STG_WORDS * 4;
            const __half* Ak = Aptr + (size_t)(kt + STAGES - 1) * BKH;
            const __half* Bk = Bptr + (size_t)(kt + STAGES - 1) * BKH;
            cp_async16(sb + a_off0, Ak);
            cp_async16(sb + a_off1, Ak + (size_t)64 * K);
            cp_async16(sb + b_off0, Bk);
            cp_async16(sb + b_off1, Bk + (size_t)64 * K);
        }
        cp_commit();

        const uint32_t* Ab = gsm + (kt & (STAGES - 1)) * STG_WORDS;
        const uint32_t* Bb = Ab + A_WORDS;

        // two k16 blocks per stage: kword base kb = ks*8
        #pragma unroll
        for (int ks = 0; ks < 2; ks++) {
            const int kb = ks * 8;
            uint32_t afr[4][4];
            #pragma unroll
            for (int mi = 0; mi < 4; mi++) {
                int rb = (wm * 64 + mi * 16 + qr) * LDW + kb + qc;
                afr[mi][0] = Ab[rb];
                afr[mi][1] = Ab[rb + 8 * LDW];
                afr[mi][2] = Ab[rb + 4];
                afr[mi][3] = Ab[rb + 8 * LDW + 4];
            }
            uint32_t bfr[4][2];
            #pragma unroll
            for (int ni = 0; ni < 4; ni++) {
                int cb = (wn * 32 + ni * 8 + qr) * LDW + kb + qc;
                bfr[ni][0] = Bb[cb];
                bfr[ni][1] = Bb[cb + 4];
            }
            #pragma unroll
            for (int mi = 0; mi < 4; mi++)
                #pragma unroll
                for (int ni = 0; ni < 4; ni++)
                    mma_f16(acc[mi][ni], afr[mi], bfr[ni]);
        }
    }

    // Epilogue: bias + store f32
    #pragma unroll
    for (int ni = 0; ni < 4; ni++) {
        int col = n0 + wn * 32 + ni * 8 + qc * 2;
        float2 bv = *(const float2*)(bias + col);
        #pragma unroll
        for (int mi = 0; mi < 4; mi++) {
            int row = m0 + wm * 64 + mi * 16 + qr;
            float2 o0, o1;
            o0.x = acc[mi][ni][0] + bv.x;
            o0.y = acc[mi][ni][1] + bv.y;
            o1.x = acc[mi][ni][2] + bv.x;
            o1.y = acc[mi][ni][3] + bv.y;
            *(float2*)(C + (size_t)row * N + col)       = o0;
            *(float2*)(C + (size_t)(row + 8) * N + col) = o1;
        }
    }
}

// ---------------------------------------------------------------------------
// TF32 mma.sync flash attention (round-3 internals; output stored as fp16
// so the proj GEMM can cp.async it directly).
// ---------------------------------------------------------------------------
#define AT_FLOATS (3 * 64 * 68 + 64 * 72)
#define AT_BYTES  (AT_FLOATS * 4)

__global__ __launch_bounds__(128) void attn_tc_kernel(
    const float* __restrict__ qkv, __half* __restrict__ out)
{
    const int bid = blockIdx.x;
    const int qt  = bid & 7;
    const int h   = (bid >> 3) % H_;
    const int b   = bid / (H_ * 8);

    const int tid  = threadIdx.x;
    const int lane = tid & 31;
    const int warp = tid >> 5;
    const int qr   = lane >> 2;
    const int qc   = lane & 3;
    const int R    = warp * 16;

    extern __shared__ uint32_t smu[];
    uint32_t* Qs = smu;                 // [64][68]
    uint32_t* Ks = smu + 64 * 68;       // [64][68]
    uint32_t* Ps = smu + 2 * 64 * 68;   // [64][68]
    uint32_t* Vs = smu + 3 * 64 * 68;   // [64][72]

    const float* qbase = qkv + (size_t)(b * S_ + qt * 64) * QKV_N + h * HD_;

    for (int t = tid; t < 1024; t += 128) {
        int r  = t >> 4;
        int c4 = (t & 15) << 2;
        float4 v = *(const float4*)(qbase + (size_t)r * QKV_N + c4);
        *(uint4*)&Qs[r * 68 + c4] =
            make_uint4(f2tf32(v.x * QSC), f2tf32(v.y * QSC),
                       f2tf32(v.z * QSC), f2tf32(v.w * QSC));
    }

    float m1 = -1e30f, m2 = -1e30f, l1 = 0.0f, l2 = 0.0f;
    float o[8][4];
    #pragma unroll
    for (int nt = 0; nt < 8; nt++)
        #pragma unroll
        for (int r = 0; r < 4; r++) o[nt][r] = 0.0f;

    for (int kt = 0; kt < 8; kt++) {
        const float* kbase = qkv + (size_t)(b * S_ + kt * 64) * QKV_N + D_ + h * HD_;
        const float* vbase = kbase + D_;

        __syncthreads();
        for (int t = tid; t < 1024; t += 128) {
            int r  = t >> 4;
            int c4 = (t & 15) << 2;
            float4 kk = *(const float4*)(kbase + (size_t)r * QKV_N + c4);
            *(uint4*)&Ks[r * 68 + c4] =
                make_uint4(f2tf32(kk.x), f2tf32(kk.y), f2tf32(kk.z), f2tf32(kk.w));
            float4 vv = *(const float4*)(vbase + (size_t)r * QKV_N + c4);
            *(uint4*)&Vs[r * 72 + c4] =
                make_uint4(f2tf32(vv.x), f2tf32(vv.y), f2tf32(vv.z), f2tf32(vv.w));
        }
        __syncthreads();

        float s[8][4];
        #pragma unroll
        for (int nt = 0; nt < 8; nt++)
            #pragma unroll
            for (int r = 0; r < 4; r++) s[nt][r] = 0.0f;

        #pragma unroll
        for (int k8 = 0; k8 < HD_; k8 += 8) {
            uint32_t a[4];
            a[0] = Qs[(R + qr) * 68 + k8 + qc];
            a[1] = Qs[(R + qr + 8) * 68 + k8 + qc];
            a[2] = Qs[(R + qr) * 68 + k8 + qc + 4];
            a[3] = Qs[(R + qr + 8) * 68 + k8 + qc + 4];
            #pragma unroll
            for (int nt = 0; nt < 8; nt++) {
                uint32_t bb[2];
                bb[0] = Ks[(nt * 8 + qr) * 68 + k8 + qc];
                bb[1] = Ks[(nt * 8 + qr) * 68 + k8 + qc + 4];
                mma_tf32(s[nt], a, bb);
            }
        }

        float mx1 = -1e30f, mx2 = -1e30f;
        #pragma unroll
        for (int nt = 0; nt < 8; nt++) {
            mx1 = fmaxf(mx1, fmaxf(s[nt][0], s[nt][1]));
            mx2 = fmaxf(mx2, fmaxf(s[nt][2], s[nt][3]));
        }
        mx1 = fmaxf(mx1, __shfl_xor_sync(0xffffffffu, mx1, 1));
        mx1 = fmaxf(mx1, __shfl_xor_sync(0xffffffffu, mx1, 2));
        mx2 = fmaxf(mx2, __shfl_xor_sync(0xffffffffu, mx2, 1));
        mx2 = fmaxf(mx2, __shfl_xor_sync(0xffffffffu, mx2, 2));

        float mn1 = fmaxf(m1, mx1);
        float mn2 = fmaxf(m2, mx2);
        float c1 = exp2f(m1 - mn1);
        float c2 = exp2f(m2 - mn2);
        m1 = mn1; m2 = mn2;

        float rs1 = 0.0f, rs2 = 0.0f;
        #pragma unroll
        for (int nt = 0; nt < 8; nt++) {
            s[nt][0] = exp2_poly(s[nt][0] - mn1);
            s[nt][1] = exp2_poly(s[nt][1] - mn1);
            s[nt][2] = exp2_poly(s[nt][2] - mn2);
            s[nt][3] = exp2_poly(s[nt][3] - mn2);
            rs1 += s[nt][0] + s[nt][1];
            rs2 += s[nt][2] + s[nt][3];
        }
        rs1 += __shfl_xor_sync(0xffffffffu, rs1, 1);
        rs1 += __shfl_xor_sync(0xffffffffu, rs1, 2);
        rs2 += __shfl_xor_sync(0xffffffffu, rs2, 1);
        rs2 += __shfl_xor_sync(0xffffffffu, rs2, 2);
        l1 = l1 * c1 + rs1;
        l2 = l2 * c2 + rs2;

        #pragma unroll
        for (int nt = 0; nt < 8; nt++) {
            o[nt][0] *= c1; o[nt][1] *= c1;
            o[nt][2] *= c2; o[nt][3] *= c2;
        }

        #pragma unroll
        for (int nt = 0; nt < 8; nt++) {
            *(uint2*)&Ps[(R + qr) * 68 + nt * 8 + 2 * qc] =
                make_uint2(f2tf32(s[nt][0]), f2tf32(s[nt][1]));
            *(uint2*)&Ps[(R + qr + 8) * 68 + nt * 8 + 2 * qc] =
                make_uint2(f2tf32(s[nt][2]), f2tf32(s[nt][3]));
        }
        __syncwarp();

        #pragma unroll
        for (int k8 = 0; k8 < 64; k8 += 8) {
            uint32_t a[4];
            a[0] = Ps[(R + qr) * 68 + k8 + qc];
            a[1] = Ps[(R + qr + 8) * 68 + k8 + qc];
            a[2] = Ps[(R + qr) * 68 + k8 + qc + 4];
            a[3] = Ps[(R + qr + 8) * 68 + k8 + qc + 4];
            #pragma unroll
            for (int nt = 0; nt < 8; nt++) {
                uint32_t bb[2];
                bb[0] = Vs[(k8 + qc) * 72 + nt * 8 + qr];
                bb[1] = Vs[(k8 + qc + 4) * 72 + nt * 8 + qr];
                mma_tf32(o[nt], a, bb);
            }
        }
        __syncwarp();
    }

    // Normalize + store fp16 (consumed only by proj GEMM)
    float i1 = 1.0f / l1;
    float i2 = 1.0f / l2;
    __half* ob = out + (size_t)(b * S_ + qt * 64) * D_ + h * HD_;
    #pragma unroll
    for (int nt = 0; nt < 8; nt++) {
        int col = nt * 8 + 2 * qc;
        __half2 w0 = __floats2half2_rn(o[nt][0] * i1, o[nt][1] * i1);
        __half2 w1 = __floats2half2_rn(o[nt][2] * i2, o[nt][3] * i2);
        *(__half2*)(ob + (size_t)(R + qr) * D_ + col)     = w0;
        *(__half2*)(ob + (size_t)(R + qr + 8) * D_ + col) = w1;
    }
}

// ---------------------------------------------------------------------------
// Launch
// ---------------------------------------------------------------------------
extern "C" void kernel_launch(void* const* d_in, const int* in_sizes, int n_in,
                              void* d_out, int out_size)
{
    const float* x      = (const float*)d_in[0];
    const float* qkv_w  = (const float*)d_in[1];
    const float* qkv_b  = (const float*)d_in[2];
    const float* proj_w = (const float*)d_in[3];
    const float* proj_b = (const float*)d_in[4];
    float* out = (float*)d_out;

    void *qkv_p, *attnh_p, *xh_p, *qkvwh_p, *projwh_p;
    cudaGetSymbolAddress(&qkv_p, g_qkv);
    cudaGetSymbolAddress(&attnh_p, g_attnh);
    cudaGetSymbolAddress(&xh_p, g_xh);
    cudaGetSymbolAddress(&qkvwh_p, g_qkvwh);
    cudaGetSymbolAddress(&projwh_p, g_projwh);
    float*  qkv_s    = (float*)qkv_p;
    __half* attnh_s  = (__half*)attnh_p;
    __half* xh_s     = (__half*)xh_p;
    __half* qkvwh_s  = (__half*)qkvwh_p;
    __half* projwh_s = (__half*)projwh_p;

    cudaFuncSetAttribute(gemm_f16_kernel,
                         cudaFuncAttributeMaxDynamicSharedMemorySize,
                         GEMM_SMEM_BYTES);
    cudaFuncSetAttribute(attn_tc_kernel,
                         cudaFuncAttributeMaxDynamicSharedMemorySize,
                         AT_BYTES);

    // 0) Pre-convert inputs to fp16 (rn)
    cvt_f16_kernel<<<1024, 256>>>(x, xh_s, M_TOT * D_ / 8);
    cvt_f16_kernel<<<512, 256>>>(qkv_w, qkvwh_s, QKV_N * D_ / 8);
    cvt_f16_kernel<<<256, 256>>>(proj_w, projwh_s, D_ * D_ / 8);

    // 1) QKV projection: [16384,768] @ [2304,768]^T + b  (fp16 in, f32 out)
    gemm_f16_kernel<<<dim3(QKV_N / BN, M_TOT / BM), 256, GEMM_SMEM_BYTES>>>(
        xh_s, qkvwh_s, qkv_b, qkv_s, M_TOT, QKV_N, D_);

    // 2) Flash attention (tf32 internals, fp16 output)
    attn_tc_kernel<<<B_ * H_ * (S_ / 64), 128, AT_BYTES>>>(qkv_s, attnh_s);

    // 3) Output projection: [16384,768] @ [768,768]^T + b  (fp16 in, f32 out)
    gemm_f16_kernel<<<dim3(D_ / BN, M_TOT / BM), 256, GEMM_SMEM_BYTES>>>(
        attnh_s, projwh_s, proj_b, out, M_TOT, D_, D_);
}

// round 11
// speedup vs baseline: 2.0345x; 1.0273x over previous
#include <cuda_runtime.h>
#include <cuda_fp16.h>
#include <cstdint>

// Problem constants
#define B_  32
#define S_  512
#define D_  768
#define H_  12
#define HD_ 64
#define SCALE_ 0.125f
// SCALE * log2(e): scores computed directly in log2 domain
#define QSC 0.18033688011112042f

#define M_TOT (B_ * S_)          // 16384
#define QKV_N (3 * D_)           // 2304

// Scratch (device globals — allocation-free)
__device__ __half g_qkvh[(size_t)M_TOT * QKV_N];   // [M, 3D] fp16 QKV (q pre-scaled by QSC)
__device__ __half g_attnh[(size_t)M_TOT * D_];     // [M, D] attn out (fp16)
__device__ __half g_xh[(size_t)M_TOT * D_];        // x as fp16
__device__ __half g_qkvwh[(size_t)QKV_N * D_];     // qkv_w as fp16
__device__ __half g_projwh[(size_t)D_ * D_];       // proj_w as fp16

// ---------------------------------------------------------------------------
// Helpers
// ---------------------------------------------------------------------------
__device__ __forceinline__ void mma_f16(float d[4], const uint32_t a[4],
                                        const uint32_t b[2]) {
    asm volatile(
        "mma.sync.aligned.m16n8k16.row.col.f32.f16.f16.f32 "
        "{%0,%1,%2,%3},{%4,%5,%6,%7},{%8,%9},{%0,%1,%2,%3};\n"
        : "+f"(d[0]), "+f"(d[1]), "+f"(d[2]), "+f"(d[3])
        : "r"(a[0]), "r"(a[1]), "r"(a[2]), "r"(a[3]),
          "r"(b[0]), "r"(b[1]));
}

__device__ __forceinline__ void cp_async16(uint32_t saddr, const void* gptr) {
    asm volatile("cp.async.cg.shared.global [%0], [%1], 16;"
                 :: "r"(saddr), "l"(gptr));
}
__device__ __forceinline__ void cp_commit() {
    asm volatile("cp.async.commit_group;");
}
template <int N>
__device__ __forceinline__ void cp_wait() {
    asm volatile("cp.async.wait_group %0;" :: "n"(N));
}

// 2^t on the FMA pipe only.
__device__ __forceinline__ float exp2_poly(float t) {
    float g  = t + 12582912.0f;
    int   j  = __float_as_int(g);
    float nf = g - 12582912.0f;
    float f  = t - nf;
    float p  = 0.0096181f;
    p = fmaf(p, f, 0.0555041f);
    p = fmaf(p, f, 0.2402265f);
    p = fmaf(p, f, 0.6931472f);
    p = fmaf(p, f, 1.0f);
    int n = j - 0x4B400000;
    return __int_as_float(__float_as_int(p) + (n << 23));
}

// ---------------------------------------------------------------------------
// Elementwise f32 -> fp16 (rn) pre-convert pass. 8 elems/iter.
// ---------------------------------------------------------------------------
__global__ void cvt_f16_kernel(const float* __restrict__ in,
                               __half* __restrict__ out, int n8)
{
    int i = blockIdx.x * blockDim.x + threadIdx.x;
    int step = gridDim.x * blockDim.x;
    for (; i < n8; i += step) {
        float4 v0 = *(const float4*)(in + (size_t)i * 8);
        float4 v1 = *(const float4*)(in + (size_t)i * 8 + 4);
        __half2 h0 = __floats2half2_rn(v0.x, v0.y);
        __half2 h1 = __floats2half2_rn(v0.z, v0.w);
        __half2 h2 = __floats2half2_rn(v1.x, v1.y);
        __half2 h3 = __floats2half2_rn(v1.z, v1.w);
        uint4 o;
        o.x = *(uint32_t*)&h0; o.y = *(uint32_t*)&h1;
        o.z = *(uint32_t*)&h2; o.w = *(uint32_t*)&h3;
        *(uint4*)(out + (size_t)i * 8) = o;
    }
}

// ---------------------------------------------------------------------------
// FP16 tensor-core GEMM with 4-stage cp.async pipeline.
// C[M,N] = A[M,K] @ B[N,K]^T + bias[N]
// HOUT: store fp16 (and scale cols<768 by QSC — QKV GEMM q-block pre-scale).
// BM=BN=128, BK=32 halfs. 256 threads = 8 warps (2x4), warp tile 64x32.
// ---------------------------------------------------------------------------
#define BM 128
#define BN 128
#define BKH 32
#define LDW 20
#define STAGES 4
#define A_WORDS (BM * LDW)
#define STG_WORDS ((BM + BN) * LDW)
#define GEMM_SMEM_BYTES (STAGES * STG_WORDS * 4)   // 81920

template <bool HOUT>
__global__ __launch_bounds__(256) void gemm_f16_kernel(
    const __half* __restrict__ A, const __half* __restrict__ Bw,
    const float* __restrict__ bias, void* __restrict__ Cv,
    int M, int N, int K)
{
    extern __shared__ uint32_t gsm[];

    const int tid  = threadIdx.x;
    const int lane = tid & 31;
    const int warp = tid >> 5;
    const int wm   = warp >> 2;
    const int wn   = warp & 3;
    const int m0   = blockIdx.y * BM;
    const int n0   = blockIdx.x * BN;

    const int lrow = tid >> 2;
    const int lq   = tid & 3;

    const __half* Aptr = A  + (size_t)(m0 + lrow) * K + lq * 8;
    const __half* Bptr = Bw + (size_t)(n0 + lrow) * K + lq * 8;

    const uint32_t smem_base = (uint32_t)__cvta_generic_to_shared(gsm);
    const uint32_t a_off0 = ((lrow)      * LDW + lq * 4) * 4;
    const uint32_t a_off1 = ((lrow + 64) * LDW + lq * 4) * 4;
    const uint32_t b_off0 = (A_WORDS + (lrow)      * LDW + lq * 4) * 4;
    const uint32_t b_off1 = (A_WORDS + (lrow + 64) * LDW + lq * 4) * 4;

    const int nk = K / BKH;

    float acc[4][4][4];
    #pragma unroll
    for (int mi = 0; mi < 4; mi++)
        #pragma unroll
        for (int ni = 0; ni < 4; ni++)
            #pragma unroll
            for (int r = 0; r < 4; r++) acc[mi][ni][r] = 0.0f;

    #pragma unroll
    for (int s = 0; s < STAGES - 1; s++) {
        uint32_t sb = smem_base + s * STG_WORDS * 4;
        const __half* Ak = Aptr + (size_t)s * BKH;
        const __half* Bk = Bptr + (size_t)s * BKH;
        cp_async16(sb + a_off0, Ak);
        cp_async16(sb + a_off1, Ak + (size_t)64 * K);
        cp_async16(sb + b_off0, Bk);
        cp_async16(sb + b_off1, Bk + (size_t)64 * K);
        cp_commit();
    }

    const int qr = lane >> 2;
    const int qc = lane & 3;

    for (int kt = 0; kt < nk; kt++) {
        cp_wait<STAGES - 2>();
        __syncthreads();

        if (kt + STAGES - 1 < nk) {
            int s = (kt + STAGES - 1) & (STAGES - 1);
            uint32_t sb = smem_base + s * STG_WORDS * 4;
            const __half* Ak = Aptr + (size_t)(kt + STAGES - 1) * BKH;
            const __half* Bk = Bptr + (size_t)(kt + STAGES - 1) * BKH;
            cp_async16(sb + a_off0, Ak);
            cp_async16(sb + a_off1, Ak + (size_t)64 * K);
            cp_async16(sb + b_off0, Bk);
            cp_async16(sb + b_off1, Bk + (size_t)64 * K);
        }
        cp_commit();

        const uint32_t* Ab = gsm + (kt & (STAGES - 1)) * STG_WORDS;
        const uint32_t* Bb = Ab + A_WORDS;

        #pragma unroll
        for (int ks = 0; ks < 2; ks++) {
            const int kb = ks * 8;
            uint32_t afr[4][4];
            #pragma unroll
            for (int mi = 0; mi < 4; mi++) {
                int rb = (wm * 64 + mi * 16 + qr) * LDW + kb + qc;
                afr[mi][0] = Ab[rb];
                afr[mi][1] = Ab[rb + 8 * LDW];
                afr[mi][2] = Ab[rb + 4];
                afr[mi][3] = Ab[rb + 8 * LDW + 4];
            }
            uint32_t bfr[4][2];
            #pragma unroll
            for (int ni = 0; ni < 4; ni++) {
                int cb = (wn * 32 + ni * 8 + qr) * LDW + kb + qc;
                bfr[ni][0] = Bb[cb];
                bfr[ni][1] = Bb[cb + 4];
            }
            #pragma unroll
            for (int mi = 0; mi < 4; mi++)
                #pragma unroll
                for (int ni = 0; ni < 4; ni++)
                    mma_f16(acc[mi][ni], afr[mi], bfr[ni]);
        }
    }

    // Epilogue
    #pragma unroll
    for (int ni = 0; ni < 4; ni++) {
        int col = n0 + wn * 32 + ni * 8 + qc * 2;
        float2 bv = *(const float2*)(bias + col);
        float scl = 1.0f;
        if (HOUT && col < D_) scl = QSC;   // q-block pre-scale (log2 domain)
        #pragma unroll
        for (int mi = 0; mi < 4; mi++) {
            int row = m0 + wm * 64 + mi * 16 + qr;
            float o00 = (acc[mi][ni][0] + bv.x) * scl;
            float o01 = (acc[mi][ni][1] + bv.y) * scl;
            float o10 = (acc[mi][ni][2] + bv.x) * scl;
            float o11 = (acc[mi][ni][3] + bv.y) * scl;
            if (HOUT) {
                __half* Ch = (__half*)Cv;
                *(__half2*)(Ch + (size_t)row * N + col) =
                    __floats2half2_rn(o00, o01);
                *(__half2*)(Ch + (size_t)(row + 8) * N + col) =
                    __floats2half2_rn(o10, o11);
            } else {
                float* Cf = (float*)Cv;
                *(float2*)(Cf + (size_t)row * N + col) = make_float2(o00, o01);
                *(float2*)(Cf + (size_t)(row + 8) * N + col) = make_float2(o10, o11);
            }
        }
    }
}

// ---------------------------------------------------------------------------
// FP16 tensor-core flash attention.
// Block = (b, h, 64-row q tile); 128 threads = 4 warps, warp owns 16 q rows.
// qkv is fp16, q already scaled by QSC (log2-domain scores).
// smem (words, stride 36 per 64-half row): Qs, Ks, Ps, Vt  (Vt = [d][seq])
// ---------------------------------------------------------------------------
#define AST 36                         // smem row stride in words
#define AT_WORDS (4 * 64 * AST)        // 9216 words
#define AT_BYTES (AT_WORDS * 4)        // 36864

__global__ __launch_bounds__(128) void attn_f16_kernel(
    const __half* __restrict__ qkv, __half* __restrict__ out)
{
    const int bid = blockIdx.x;
    const int qt  = bid & 7;
    const int h   = (bid >> 3) % H_;
    const int b   = bid / (H_ * 8);

    const int tid  = threadIdx.x;
    const int lane = tid & 31;
    const int warp = tid >> 5;
    const int qr   = lane >> 2;
    const int qc   = lane & 3;
    const int R    = warp * 16;

    extern __shared__ uint32_t smu[];
    uint32_t* Qs = smu;                 // [64][AST]
    uint32_t* Ks = smu + 64 * AST;      // [64][AST]
    uint32_t* Ps = smu + 2 * 64 * AST;  // [64][AST]
    uint32_t* Vt = smu + 3 * 64 * AST;  // [64 d][AST] (transposed V)

    const __half* qbase = qkv + (size_t)(b * S_ + qt * 64) * QKV_N + h * HD_;

    // Load Q tile (fp16 copy, already scaled): 64 rows x 64 halves
    for (int t = tid; t < 512; t += 128) {
        int r = t >> 3;
        int c = t & 7;                  // 8-half chunk
        uint4 v = *(const uint4*)(qbase + (size_t)r * QKV_N + c * 8);
        *(uint4*)&Qs[r * AST + c * 4] = v;
    }

    float m1 = -1e30f, m2 = -1e30f, l1 = 0.0f, l2 = 0.0f;
    float o[8][4];
    #pragma unroll
    for (int nt = 0; nt < 8; nt++)
        #pragma unroll
        for (int r = 0; r < 4; r++) o[nt][r] = 0.0f;

    for (int kt = 0; kt < 8; kt++) {
        const __half* kbase = qkv + (size_t)(b * S_ + kt * 64) * QKV_N + D_ + h * HD_;
        const __half* vbase = kbase + D_;

        __syncthreads();   // prior PV reads of Ks/Vt done
        // K tile: straight fp16 copy
        for (int t = tid; t < 512; t += 128) {
            int r = t >> 3;
            int c = t & 7;
            uint4 v = *(const uint4*)(kbase + (size_t)r * QKV_N + c * 8);
            *(uint4*)&Ks[r * AST + c * 4] = v;
        }
        // V tile: transpose into Vt[d][seq] (b16 scatter)
        for (int t = tid; t < 1024; t += 128) {
            int r  = t >> 4;            // seq 0..63
            int c4 = (t & 15) << 2;     // d base 0,4,..,60
            uint2 v = *(const uint2*)(vbase + (size_t)r * QKV_N + c4);
            const __half* hv = (const __half*)&v;
            __half* vt = (__half*)Vt;
            vt[(c4 + 0) * (2 * AST) + r] = hv[0];
            vt[(c4 + 1) * (2 * AST) + r] = hv[1];
            vt[(c4 + 2) * (2 * AST) + r] = hv[2];
            vt[(c4 + 3) * (2 * AST) + r] = hv[3];
        }
        __syncthreads();

        // S = Q K^T  (log2 domain; fp16 MMA, f32 accum)
        float s[8][4];
        #pragma unroll
        for (int nt = 0; nt < 8; nt++)
            #pragma unroll
            for (int r = 0; r < 4; r++) s[nt][r] = 0.0f;

        #pragma unroll
        for (int ks = 0; ks < 4; ks++) {         // 4 k16 steps over HD=64
            const int kb = ks * 8;               // word base
            uint32_t a[4];
            a[0] = Qs[(R + qr) * AST + kb + qc];
            a[1] = Qs[(R + qr + 8) * AST + kb + qc];
            a[2] = Qs[(R + qr) * AST + kb + qc + 4];
            a[3] = Qs[(R + qr + 8) * AST + kb + qc + 4];
            #pragma unroll
            for (int nt = 0; nt < 8; nt++) {
                uint32_t bb[2];
                bb[0] = Ks[(nt * 8 + qr) * AST + kb + qc];
                bb[1] = Ks[(nt * 8 + qr) * AST + kb + qc + 4];
                mma_f16(s[nt], a, bb);
            }
        }

        // Online softmax (base-2)
        float mx1 = -1e30f, mx2 = -1e30f;
        #pragma unroll
        for (int nt = 0; nt < 8; nt++) {
            mx1 = fmaxf(mx1, fmaxf(s[nt][0], s[nt][1]));
            mx2 = fmaxf(mx2, fmaxf(s[nt][2], s[nt][3]));
        }
        mx1 = fmaxf(mx1, __shfl_xor_sync(0xffffffffu, mx1, 1));
        mx1 = fmaxf(mx1, __shfl_xor_sync(0xffffffffu, mx1, 2));
        mx2 = fmaxf(mx2, __shfl_xor_sync(0xffffffffu, mx2, 1));
        mx2 = fmaxf(mx2, __shfl_xor_sync(0xffffffffu, mx2, 2));

        float mn1 = fmaxf(m1, mx1);
        float mn2 = fmaxf(m2, mx2);
        float c1 = exp2f(m1 - mn1);
        float c2 = exp2f(m2 - mn2);
        m1 = mn1; m2 = mn2;

        float rs1 = 0.0f, rs2 = 0.0f;
        #pragma unroll
        for (int nt = 0; nt < 8; nt++) {
            s[nt][0] = exp2_poly(s[nt][0] - mn1);
            s[nt][1] = exp2_poly(s[nt][1] - mn1);
            s[nt][2] = exp2_poly(s[nt][2] - mn2);
            s[nt][3] = exp2_poly(s[nt][3] - mn2);
            rs1 += s[nt][0] + s[nt][1];
            rs2 += s[nt][2] + s[nt][3];
        }
        rs1 += __shfl_xor_sync(0xffffffffu, rs1, 1);
        rs1 += __shfl_xor_sync(0xffffffffu, rs1, 2);
        rs2 += __shfl_xor_sync(0xffffffffu, rs2, 1);
        rs2 += __shfl_xor_sync(0xffffffffu, rs2, 2);
        l1 = l1 * c1 + rs1;
        l2 = l2 * c2 + rs2;

        #pragma unroll
        for (int nt = 0; nt < 8; nt++) {
            o[nt][0] *= c1; o[nt][1] *= c1;
            o[nt][2] *= c2; o[nt][3] *= c2;
        }

        // Stage P (fp16) into warp-private Ps rows: cols nt*8 + 2qc, 2qc+1
        #pragma unroll
        for (int nt = 0; nt < 8; nt++) {
            __half2 p0 = __floats2half2_rn(s[nt][0], s[nt][1]);
            __half2 p1 = __floats2half2_rn(s[nt][2], s[nt][3]);
            Ps[(R + qr) * AST + nt * 4 + qc]     = *(uint32_t*)&p0;
            Ps[(R + qr + 8) * AST + nt * 4 + qc] = *(uint32_t*)&p1;
        }
        __syncwarp();

        // O += P @ Vt^T  (fp16 MMA; Vt rows = d)
        #pragma unroll
        for (int ks = 0; ks < 4; ks++) {
            const int kb = ks * 8;
            uint32_t a[4];
            a[0] = Ps[(R + qr) * AST + kb + qc];
            a[1] = Ps[(R + qr + 8) * AST + kb + qc];
            a[2] = Ps[(R + qr) * AST + kb + qc + 4];
            a[3] = Ps[(R + qr + 8) * AST + kb + qc + 4];
            #pragma unroll
            for (int nt = 0; nt < 8; nt++) {
                uint32_t bb[2];
                bb[0] = Vt[(nt * 8 + qr) * AST + kb + qc];
                bb[1] = Vt[(nt * 8 + qr) * AST + kb + qc + 4];
                mma_f16(o[nt], a, bb);
            }
        }
        __syncwarp();
    }

    // Normalize + store fp16 (consumed only by proj GEMM)
    float i1 = 1.0f / l1;
    float i2 = 1.0f / l2;
    __half* ob = out + (size_t)(b * S_ + qt * 64) * D_ + h * HD_;
    #pragma unroll
    for (int nt = 0; nt < 8; nt++) {
        int col = nt * 8 + 2 * qc;
        __half2 w0 = __floats2half2_rn(o[nt][0] * i1, o[nt][1] * i1);
        __half2 w1 = __floats2half2_rn(o[nt][2] * i2, o[nt][3] * i2);
        *(__half2*)(ob + (size_t)(R + qr) * D_ + col)     = w0;
        *(__half2*)(ob + (size_t)(R + qr + 8) * D_ + col) = w1;
    }
}

// ---------------------------------------------------------------------------
// Launch
// ---------------------------------------------------------------------------
extern "C" void kernel_launch(void* const* d_in, const int* in_sizes, int n_in,
                              void* d_out, int out_size)
{
    const float* x      = (const float*)d_in[0];
    const float* qkv_w  = (const float*)d_in[1];
    const float* qkv_b  = (const float*)d_in[2];
    const float* proj_w = (const float*)d_in[3];
    const float* proj_b = (const float*)d_in[4];
    float* out = (float*)d_out;

    void *qkvh_p, *attnh_p, *xh_p, *qkvwh_p, *projwh_p;
    cudaGetSymbolAddress(&qkvh_p, g_qkvh);
    cudaGetSymbolAddress(&attnh_p, g_attnh);
    cudaGetSymbolAddress(&xh_p, g_xh);
    cudaGetSymbolAddress(&qkvwh_p, g_qkvwh);
    cudaGetSymbolAddress(&projwh_p, g_projwh);
    __half* qkvh_s   = (__half*)qkvh_p;
    __half* attnh_s  = (__half*)attnh_p;
    __half* xh_s     = (__half*)xh_p;
    __half* qkvwh_s  = (__half*)qkvwh_p;
    __half* projwh_s = (__half*)projwh_p;

    cudaFuncSetAttribute(gemm_f16_kernel<true>,
                         cudaFuncAttributeMaxDynamicSharedMemorySize,
                         GEMM_SMEM_BYTES);
    cudaFuncSetAttribute(gemm_f16_kernel<false>,
                         cudaFuncAttributeMaxDynamicSharedMemorySize,
                         GEMM_SMEM_BYTES);
    cudaFuncSetAttribute(attn_f16_kernel,
                         cudaFuncAttributeMaxDynamicSharedMemorySize,
                         AT_BYTES);

    // 0) Pre-convert inputs to fp16 (rn)
    cvt_f16_kernel<<<1024, 256>>>(x, xh_s, M_TOT * D_ / 8);
    cvt_f16_kernel<<<512, 256>>>(qkv_w, qkvwh_s, QKV_N * D_ / 8);
    cvt_f16_kernel<<<256, 256>>>(proj_w, projwh_s, D_ * D_ / 8);

    // 1) QKV projection -> fp16 qkv (q cols pre-scaled by QSC)
    gemm_f16_kernel<true><<<dim3(QKV_N / BN, M_TOT / BM), 256, GEMM_SMEM_BYTES>>>(
        xh_s, qkvwh_s, qkv_b, qkvh_s, M_TOT, QKV_N, D_);

    // 2) Flash attention (full fp16 MMA)
    attn_f16_kernel<<<B_ * H_ * (S_ / 64), 128, AT_BYTES>>>(qkvh_s, attnh_s);

    // 3) Output projection -> f32 out
    gemm_f16_kernel<false><<<dim3(D_ / BN, M_TOT / BM), 256, GEMM_SMEM_BYTES>>>(
        attnh_s, projwh_s, proj_b, out, M_TOT, D_, D_);
}

// round 13
// speedup vs baseline: 2.6413x; 1.2983x over previous
#include <cuda_runtime.h>
#include <cuda_fp16.h>
#include <cstdint>

// Problem constants
#define B_  32
#define S_  512
#define D_  768
#define H_  12
#define HD_ 64
#define SCALE_ 0.125f
// SCALE * log2(e): scores computed directly in log2 domain
#define QSC 0.18033688011112042f

#define M_TOT (B_ * S_)          // 16384
#define QKV_N (3 * D_)           // 2304

// Scratch (device globals — allocation-free)
__device__ __half g_qkvh[(size_t)M_TOT * QKV_N];   // [M, 3D] fp16 QKV (q pre-scaled)
__device__ __half g_attnh[(size_t)M_TOT * D_];     // [M, D] attn out (fp16)
__device__ __half g_xh[(size_t)M_TOT * D_];        // x as fp16
__device__ __half g_qkvwh[(size_t)QKV_N * D_];     // qkv_w as fp16
__device__ __half g_projwh[(size_t)D_ * D_];       // proj_w as fp16

// ---------------------------------------------------------------------------
// Helpers
// ---------------------------------------------------------------------------
__device__ __forceinline__ void mma_f16(float d[4], const uint32_t a[4],
                                        const uint32_t b[2]) {
    asm volatile(
        "mma.sync.aligned.m16n8k16.row.col.f32.f16.f16.f32 "
        "{%0,%1,%2,%3},{%4,%5,%6,%7},{%8,%9},{%0,%1,%2,%3};\n"
        : "+f"(d[0]), "+f"(d[1]), "+f"(d[2]), "+f"(d[3])
        : "r"(a[0]), "r"(a[1]), "r"(a[2]), "r"(a[3]),
          "r"(b[0]), "r"(b[1]));
}

__device__ __forceinline__ void ldsm_x4(uint32_t r[4], uint32_t saddr) {
    asm volatile(
        "ldmatrix.sync.aligned.m8n8.x4.shared.b16 {%0,%1,%2,%3},[%4];"
        : "=r"(r[0]), "=r"(r[1]), "=r"(r[2]), "=r"(r[3]) : "r"(saddr));
}
__device__ __forceinline__ void ldsm_x4_trans(uint32_t r[4], uint32_t saddr) {
    asm volatile(
        "ldmatrix.sync.aligned.m8n8.x4.trans.shared.b16 {%0,%1,%2,%3},[%4];"
        : "=r"(r[0]), "=r"(r[1]), "=r"(r[2]), "=r"(r[3]) : "r"(saddr));
}

__device__ __forceinline__ void cp_async16(uint32_t saddr, const void* gptr) {
    asm volatile("cp.async.cg.shared.global [%0], [%1], 16;"
                 :: "r"(saddr), "l"(gptr));
}
__device__ __forceinline__ void cp_commit() {
    asm volatile("cp.async.commit_group;");
}
template <int N>
__device__ __forceinline__ void cp_wait() {
    asm volatile("cp.async.wait_group %0;" :: "n"(N));
}

// 2^t on the FMA pipe only.
__device__ __forceinline__ float exp2_poly(float t) {
    float g  = t + 12582912.0f;
    int   j  = __float_as_int(g);
    float nf = g - 12582912.0f;
    float f  = t - nf;
    float p  = 0.0096181f;
    p = fmaf(p, f, 0.0555041f);
    p = fmaf(p, f, 0.2402265f);
    p = fmaf(p, f, 0.6931472f);
    p = fmaf(p, f, 1.0f);
    int n = j - 0x4B400000;
    return __int_as_float(__float_as_int(p) + (n << 23));
}

// ---------------------------------------------------------------------------
// Elementwise f32 -> fp16 (rn) pre-convert pass. 8 elems/iter.
// ---------------------------------------------------------------------------
__global__ void cvt_f16_kernel(const float* __restrict__ in,
                               __half* __restrict__ out, int n8)
{
    int i = blockIdx.x * blockDim.x + threadIdx.x;
    int step = gridDim.x * blockDim.x;
    for (; i < n8; i += step) {
        float4 v0 = *(const float4*)(in + (size_t)i * 8);
        float4 v1 = *(const float4*)(in + (size_t)i * 8 + 4);
        __half2 h0 = __floats2half2_rn(v0.x, v0.y);
        __half2 h1 = __floats2half2_rn(v0.z, v0.w);
        __half2 h2 = __floats2half2_rn(v1.x, v1.y);
        __half2 h3 = __floats2half2_rn(v1.z, v1.w);
        uint4 o;
        o.x = *(uint32_t*)&h0; o.y = *(uint32_t*)&h1;
        o.z = *(uint32_t*)&h2; o.w = *(uint32_t*)&h3;
        *(uint4*)(out + (size_t)i * 8) = o;
    }
}

// ---------------------------------------------------------------------------
// FP16 tensor-core GEMM: 4-stage cp.async pipeline + ldmatrix fragment feed.
// C[M,N] = A[M,K] @ B[N,K]^T + bias[N]
// BM=BN=128, BK=32 halfs. 256 threads = 8 warps (2x4), warp tile 64x32.
// ---------------------------------------------------------------------------
#define BM 128
#define BN 128
#define BKH 32
#define LDW 20
#define STAGES 4
#define A_WORDS (BM * LDW)
#define STG_WORDS ((BM + BN) * LDW)
#define GEMM_SMEM_BYTES (STAGES * STG_WORDS * 4)   // 81920

template <bool HOUT>
__global__ __launch_bounds__(256) void gemm_f16_kernel(
    const __half* __restrict__ A, const __half* __restrict__ Bw,
    const float* __restrict__ bias, void* __restrict__ Cv,
    int M, int N, int K)
{
    extern __shared__ uint32_t gsm[];

    const int tid  = threadIdx.x;
    const int lane = tid & 31;
    const int warp = tid >> 5;
    const int wm   = warp >> 2;
    const int wn   = warp & 3;
    const int m0   = blockIdx.y * BM;
    const int n0   = blockIdx.x * BN;

    const int lrow = tid >> 2;
    const int lq   = tid & 3;

    const __half* Aptr = A  + (size_t)(m0 + lrow) * K + lq * 8;
    const __half* Bptr = Bw + (size_t)(n0 + lrow) * K + lq * 8;

    const uint32_t smem_base = (uint32_t)__cvta_generic_to_shared(gsm);
    const uint32_t a_off0 = ((lrow)      * LDW + lq * 4) * 4;
    const uint32_t a_off1 = ((lrow + 64) * LDW + lq * 4) * 4;
    const uint32_t b_off0 = (A_WORDS + (lrow)      * LDW + lq * 4) * 4;
    const uint32_t b_off1 = (A_WORDS + (lrow + 64) * LDW + lq * 4) * 4;

    // ldmatrix lane addressing
    const int a_lr = (lane & 7) + ((lane >> 3) & 1) * 8;   // row within 16
    const int a_lk = ((lane >> 4) & 1) * 4;                // k word 0/4
    const int b_lr = (lane & 7) + ((lane >> 4) & 1) * 8;   // n within 16
    const int b_lk = ((lane >> 3) & 1) * 4;                // k word 0/4

    const int nk = K / BKH;

    float acc[4][4][4];
    #pragma unroll
    for (int mi = 0; mi < 4; mi++)
        #pragma unroll
        for (int ni = 0; ni < 4; ni++)
            #pragma unroll
            for (int r = 0; r < 4; r++) acc[mi][ni][r] = 0.0f;

    #pragma unroll
    for (int s = 0; s < STAGES - 1; s++) {
        uint32_t sb = smem_base + s * STG_WORDS * 4;
        const __half* Ak = Aptr + (size_t)s * BKH;
        const __half* Bk = Bptr + (size_t)s * BKH;
        cp_async16(sb + a_off0, Ak);
        cp_async16(sb + a_off1, Ak + (size_t)64 * K);
        cp_async16(sb + b_off0, Bk);
        cp_async16(sb + b_off1, Bk + (size_t)64 * K);
        cp_commit();
    }

    const int qr = lane >> 2;
    const int qc = lane & 3;

    for (int kt = 0; kt < nk; kt++) {
        cp_wait<STAGES - 2>();
        __syncthreads();

        if (kt + STAGES - 1 < nk) {
            int s = (kt + STAGES - 1) & (STAGES - 1);
            uint32_t sb = smem_base + s * STG_WORDS * 4;
            const __half* Ak = Aptr + (size_t)(kt + STAGES - 1) * BKH;
            const __half* Bk = Bptr + (size_t)(kt + STAGES - 1) * BKH;
            cp_async16(sb + a_off0, Ak);
            cp_async16(sb + a_off1, Ak + (size_t)64 * K);
            cp_async16(sb + b_off0, Bk);
            cp_async16(sb + b_off1, Bk + (size_t)64 * K);
        }
        cp_commit();

        const uint32_t stg = smem_base + (kt & (STAGES - 1)) * STG_WORDS * 4;

        #pragma unroll
        for (int ks = 0; ks < 2; ks++) {
            const int kb = ks * 8;
            uint32_t afr[4][4];
            #pragma unroll
            for (int mi = 0; mi < 4; mi++)
                ldsm_x4(afr[mi],
                        stg + ((wm * 64 + mi * 16 + a_lr) * LDW + kb + a_lk) * 4);
            uint32_t bfr[2][4];
            #pragma unroll
            for (int p = 0; p < 2; p++)
                ldsm_x4(bfr[p],
                        stg + (A_WORDS + (wn * 32 + p * 16 + b_lr) * LDW + kb + b_lk) * 4);
            #pragma unroll
            for (int mi = 0; mi < 4; mi++)
                #pragma unroll
                for (int p = 0; p < 2; p++) {
                    mma_f16(acc[mi][2 * p],     afr[mi], &bfr[p][0]);
                    mma_f16(acc[mi][2 * p + 1], afr[mi], &bfr[p][2]);
                }
        }
    }

    // Epilogue
    #pragma unroll
    for (int ni = 0; ni < 4; ni++) {
        int col = n0 + wn * 32 + ni * 8 + qc * 2;
        float2 bv = *(const float2*)(bias + col);
        float scl = 1.0f;
        if (HOUT && col < D_) scl = QSC;   // q-block pre-scale (log2 domain)
        #pragma unroll
        for (int mi = 0; mi < 4; mi++) {
            int row = m0 + wm * 64 + mi * 16 + qr;
            float o00 = (acc[mi][ni][0] + bv.x) * scl;
            float o01 = (acc[mi][ni][1] + bv.y) * scl;
            float o10 = (acc[mi][ni][2] + bv.x) * scl;
            float o11 = (acc[mi][ni][3] + bv.y) * scl;
            if (HOUT) {
                __half* Ch = (__half*)Cv;
                *(__half2*)(Ch + (size_t)row * N + col) =
                    __floats2half2_rn(o00, o01);
                *(__half2*)(Ch + (size_t)(row + 8) * N + col) =
                    __floats2half2_rn(o10, o11);
            } else {
                float* Cf = (float*)Cv;
                *(float2*)(Cf + (size_t)row * N + col) = make_float2(o00, o01);
                *(float2*)(Cf + (size_t)(row + 8) * N + col) = make_float2(o10, o11);
            }
        }
    }
}

// ---------------------------------------------------------------------------
// FP16 flash attention, ldmatrix fragment feed, trans-ldmatrix V (no scatter).
// Block = (b, h, 64-row q tile); 128 threads = 4 warps, warp owns 16 q rows.
// smem (words, stride AST=36): Qs[64], Ks[64], Ps[64], Vs[64 seq][64 d]
// ---------------------------------------------------------------------------
#define AST 36
#define AT_WORDS (4 * 64 * AST)
#define AT_BYTES (AT_WORDS * 4)        // 36864

__global__ __launch_bounds__(128) void attn_f16_kernel(
    const __half* __restrict__ qkv, __half* __restrict__ out)
{
    const int bid = blockIdx.x;
    const int qt  = bid & 7;
    const int h   = (bid >> 3) % H_;
    const int b   = bid / (H_ * 8);

    const int tid  = threadIdx.x;
    const int lane = tid & 31;
    const int warp = tid >> 5;
    const int qr   = lane >> 2;
    const int qc   = lane & 3;
    const int R    = warp * 16;

    extern __shared__ uint32_t smu[];
    uint32_t* Qs = smu;                 // [64][AST]
    uint32_t* Ks = smu + 64 * AST;      // [64][AST]
    uint32_t* Ps = smu + 2 * 64 * AST;  // [64][AST]
    uint32_t* Vs = smu + 3 * 64 * AST;  // [64 seq][AST] (row-major, d contiguous)

    const uint32_t sb  = (uint32_t)__cvta_generic_to_shared(smu);
    const uint32_t Qb  = sb;
    const uint32_t Kb  = sb + 64 * AST * 4;
    const uint32_t Pb  = sb + 2 * 64 * AST * 4;
    const uint32_t Vb  = sb + 3 * 64 * AST * 4;

    // ldmatrix lane addressing
    const int a_lr = (lane & 7) + ((lane >> 3) & 1) * 8;   // A row within 16
    const int a_lk = ((lane >> 4) & 1) * 4;                // A k word 0/4
    const int b_lr = (lane & 7) + ((lane >> 4) & 1) * 8;   // B n within 16
    const int b_lk = ((lane >> 3) & 1) * 4;                // B k word 0/4
    // trans-V: k(seq) within 16, d word offset 0/4
    const int v_lk = (lane & 7) + ((lane >> 3) & 1) * 8;
    const int v_ld = ((lane >> 4) & 1) * 4;

    const __half* qbase = qkv + (size_t)(b * S_ + qt * 64) * QKV_N + h * HD_;

    // Load Q tile (already QSC-scaled fp16): 64 rows x 64 halves
    for (int t = tid; t < 512; t += 128) {
        int r = t >> 3;
        int c = t & 7;
        uint4 v = *(const uint4*)(qbase + (size_t)r * QKV_N + c * 8);
        *(uint4*)&Qs[r * AST + c * 4] = v;
    }

    float m1 = -1e30f, m2 = -1e30f, l1 = 0.0f, l2 = 0.0f;
    float o[8][4];
    #pragma unroll
    for (int nt = 0; nt < 8; nt++)
        #pragma unroll
        for (int r = 0; r < 4; r++) o[nt][r] = 0.0f;

    for (int kt = 0; kt < 8; kt++) {
        const __half* kbase = qkv + (size_t)(b * S_ + kt * 64) * QKV_N + D_ + h * HD_;
        const __half* vbase = kbase + D_;

        __syncthreads();   // prior tile reads done
        for (int t = tid; t < 512; t += 128) {
            int r = t >> 3;
            int c = t & 7;
            uint4 kk = *(const uint4*)(kbase + (size_t)r * QKV_N + c * 8);
            *(uint4*)&Ks[r * AST + c * 4] = kk;
            uint4 vv = *(const uint4*)(vbase + (size_t)r * QKV_N + c * 8);
            *(uint4*)&Vs[r * AST + c * 4] = vv;
        }
        __syncthreads();

        // S = Q K^T  (log2 domain)
        float s[8][4];
        #pragma unroll
        for (int nt = 0; nt < 8; nt++)
            #pragma unroll
            for (int r = 0; r < 4; r++) s[nt][r] = 0.0f;

        #pragma unroll
        for (int ks = 0; ks < 4; ks++) {
            const int kb = ks * 8;
            uint32_t a[4];
            ldsm_x4(a, Qb + ((R + a_lr) * AST + kb + a_lk) * 4);
            #pragma unroll
            for (int p = 0; p < 4; p++) {
                uint32_t bb[4];
                ldsm_x4(bb, Kb + ((p * 16 + b_lr) * AST + kb + b_lk) * 4);
                mma_f16(s[2 * p],     a, &bb[0]);
                mma_f16(s[2 * p + 1], a, &bb[2]);
            }
        }

        // Online softmax (base-2)
        float mx1 = -1e30f, mx2 = -1e30f;
        #pragma unroll
        for (int nt = 0; nt < 8; nt++) {
            mx1 = fmaxf(mx1, fmaxf(s[nt][0], s[nt][1]));
            mx2 = fmaxf(mx2, fmaxf(s[nt][2], s[nt][3]));
        }
        mx1 = fmaxf(mx1, __shfl_xor_sync(0xffffffffu, mx1, 1));
        mx1 = fmaxf(mx1, __shfl_xor_sync(0xffffffffu, mx1, 2));
        mx2 = fmaxf(mx2, __shfl_xor_sync(0xffffffffu, mx2, 1));
        mx2 = fmaxf(mx2, __shfl_xor_sync(0xffffffffu, mx2, 2));

        float mn1 = fmaxf(m1, mx1);
        float mn2 = fmaxf(m2, mx2);
        float c1 = exp2f(m1 - mn1);
        float c2 = exp2f(m2 - mn2);
        m1 = mn1; m2 = mn2;

        float rs1 = 0.0f, rs2 = 0.0f;
        #pragma unroll
        for (int nt = 0; nt < 8; nt++) {
            s[nt][0] = exp2_poly(s[nt][0] - mn1);
            s[nt][1] = exp2_poly(s[nt][1] - mn1);
            s[nt][2] = exp2_poly(s[nt][2] - mn2);
            s[nt][3] = exp2_poly(s[nt][3] - mn2);
            rs1 += s[nt][0] + s[nt][1];
            rs2 += s[nt][2] + s[nt][3];
        }
        rs1 += __shfl_xor_sync(0xffffffffu, rs1, 1);
        rs1 += __shfl_xor_sync(0xffffffffu, rs1, 2);
        rs2 += __shfl_xor_sync(0xffffffffu, rs2, 1);
        rs2 += __shfl_xor_sync(0xffffffffu, rs2, 2);
        l1 = l1 * c1 + rs1;
        l2 = l2 * c2 + rs2;

        #pragma unroll
        for (int nt = 0; nt < 8; nt++) {
            o[nt][0] *= c1; o[nt][1] *= c1;
            o[nt][2] *= c2; o[nt][3] *= c2;
        }

        // Stage P (fp16): word (nt*4 + qc) = cols nt*8 + 2qc, +1
        #pragma unroll
        for (int nt = 0; nt < 8; nt++) {
            __half2 p0 = __floats2half2_rn(s[nt][0], s[nt][1]);
            __half2 p1 = __floats2half2_rn(s[nt][2], s[nt][3]);
            Ps[(R + qr) * AST + nt * 4 + qc]     = *(uint32_t*)&p0;
            Ps[(R + qr + 8) * AST + nt * 4 + qc] = *(uint32_t*)&p1;
        }
        __syncwarp();

        // O += P @ V  (A = P rows via ldmatrix; B = V via trans-ldmatrix)
        #pragma unroll
        for (int ks = 0; ks < 4; ks++) {
            const int kb = ks * 8;
            uint32_t a[4];
            ldsm_x4(a, Pb + ((R + a_lr) * AST + kb + a_lk) * 4);
            #pragma unroll
            for (int p = 0; p < 4; p++) {
                uint32_t bb[4];
                ldsm_x4_trans(bb, Vb + ((ks * 16 + v_lk) * AST + p * 8 + v_ld) * 4);
                mma_f16(o[2 * p],     a, &bb[0]);
                mma_f16(o[2 * p + 1], a, &bb[2]);
            }
        }
        __syncwarp();
    }

    // Normalize + store fp16 (consumed only by proj GEMM)
    float i1 = 1.0f / l1;
    float i2 = 1.0f / l2;
    __half* ob = out + (size_t)(b * S_ + qt * 64) * D_ + h * HD_;
    #pragma unroll
    for (int nt = 0; nt < 8; nt++) {
        int col = nt * 8 + 2 * qc;
        __half2 w0 = __floats2half2_rn(o[nt][0] * i1, o[nt][1] * i1);
        __half2 w1 = __floats2half2_rn(o[nt][2] * i2, o[nt][3] * i2);
        *(__half2*)(ob + (size_t)(R + qr) * D_ + col)     = w0;
        *(__half2*)(ob + (size_t)(R + qr + 8) * D_ + col) = w1;
    }
}

// ---------------------------------------------------------------------------
// Launch
// ---------------------------------------------------------------------------
extern "C" void kernel_launch(void* const* d_in, const int* in_sizes, int n_in,
                              void* d_out, int out_size)
{
    const float* x      = (const float*)d_in[0];
    const float* qkv_w  = (const float*)d_in[1];
    const float* qkv_b  = (const float*)d_in[2];
    const float* proj_w = (const float*)d_in[3];
    const float* proj_b = (const float*)d_in[4];
    float* out = (float*)d_out;

    void *qkvh_p, *attnh_p, *xh_p, *qkvwh_p, *projwh_p;
    cudaGetSymbolAddress(&qkvh_p, g_qkvh);
    cudaGetSymbolAddress(&attnh_p, g_attnh);
    cudaGetSymbolAddress(&xh_p, g_xh);
    cudaGetSymbolAddress(&qkvwh_p, g_qkvwh);
    cudaGetSymbolAddress(&projwh_p, g_projwh);
    __half* qkvh_s   = (__half*)qkvh_p;
    __half* attnh_s  = (__half*)attnh_p;
    __half* xh_s     = (__half*)xh_p;
    __half* qkvwh_s  = (__half*)qkvwh_p;
    __half* projwh_s = (__half*)projwh_p;

    cudaFuncSetAttribute(gemm_f16_kernel<true>,
                         cudaFuncAttributeMaxDynamicSharedMemorySize,
                         GEMM_SMEM_BYTES);
    cudaFuncSetAttribute(gemm_f16_kernel<false>,
                         cudaFuncAttributeMaxDynamicSharedMemorySize,
                         GEMM_SMEM_BYTES);
    cudaFuncSetAttribute(attn_f16_kernel,
                         cudaFuncAttributeMaxDynamicSharedMemorySize,
                         AT_BYTES);

    // 0) Pre-convert inputs to fp16 (rn)
    cvt_f16_kernel<<<1024, 256>>>(x, xh_s, M_TOT * D_ / 8);
    cvt_f16_kernel<<<512, 256>>>(qkv_w, qkvwh_s, QKV_N * D_ / 8);
    cvt_f16_kernel<<<256, 256>>>(proj_w, projwh_s, D_ * D_ / 8);

    // 1) QKV projection -> fp16 qkv (q cols pre-scaled by QSC)
    gemm_f16_kernel<true><<<dim3(QKV_N / BN, M_TOT / BM), 256, GEMM_SMEM_BYTES>>>(
        xh_s, qkvwh_s, qkv_b, qkvh_s, M_TOT, QKV_N, D_);

    // 2) Flash attention (full fp16 MMA, ldmatrix feed)
    attn_f16_kernel<<<B_ * H_ * (S_ / 64), 128, AT_BYTES>>>(qkvh_s, attnh_s);

    // 3) Output projection -> f32 out
    gemm_f16_kernel<false><<<dim3(D_ / BN, M_TOT / BM), 256, GEMM_SMEM_BYTES>>>(
        attnh_s, projwh_s, proj_b, out, M_TOT, D_, D_);
}

// round 14
// speedup vs baseline: 2.6979x; 1.0214x over previous
#include <cuda_runtime.h>
#include <cuda_fp16.h>
#include <cstdint>

// Problem constants
#define B_  32
#define S_  512
#define D_  768
#define H_  12
#define HD_ 64
#define SCALE_ 0.125f
// SCALE * log2(e): scores computed directly in log2 domain
#define QSC 0.18033688011112042f

#define M_TOT (B_ * S_)          // 16384
#define QKV_N (3 * D_)           // 2304

// Scratch (device globals — allocation-free)
__device__ __half g_qkvh[(size_t)M_TOT * QKV_N];   // [M, 3D] fp16 QKV (q pre-scaled)
__device__ __half g_attnh[(size_t)M_TOT * D_];     // [M, D] attn out (fp16)
__device__ __half g_xh[(size_t)M_TOT * D_];        // x as fp16
__device__ __half g_qkvwh[(size_t)QKV_N * D_];     // qkv_w as fp16
__device__ __half g_projwh[(size_t)D_ * D_];       // proj_w as fp16

// ---------------------------------------------------------------------------
// Helpers
// ---------------------------------------------------------------------------
__device__ __forceinline__ void mma_f16(float d[4], const uint32_t a[4],
                                        const uint32_t b[2]) {
    asm volatile(
        "mma.sync.aligned.m16n8k16.row.col.f32.f16.f16.f32 "
        "{%0,%1,%2,%3},{%4,%5,%6,%7},{%8,%9},{%0,%1,%2,%3};\n"
        : "+f"(d[0]), "+f"(d[1]), "+f"(d[2]), "+f"(d[3])
        : "r"(a[0]), "r"(a[1]), "r"(a[2]), "r"(a[3]),
          "r"(b[0]), "r"(b[1]));
}

__device__ __forceinline__ void ldsm_x4(uint32_t r[4], uint32_t saddr) {
    asm volatile(
        "ldmatrix.sync.aligned.m8n8.x4.shared.b16 {%0,%1,%2,%3},[%4];"
        : "=r"(r[0]), "=r"(r[1]), "=r"(r[2]), "=r"(r[3]) : "r"(saddr));
}
__device__ __forceinline__ void ldsm_x4_trans(uint32_t r[4], uint32_t saddr) {
    asm volatile(
        "ldmatrix.sync.aligned.m8n8.x4.trans.shared.b16 {%0,%1,%2,%3},[%4];"
        : "=r"(r[0]), "=r"(r[1]), "=r"(r[2]), "=r"(r[3]) : "r"(saddr));
}

__device__ __forceinline__ void cp_async16(uint32_t saddr, const void* gptr) {
    asm volatile("cp.async.cg.shared.global [%0], [%1], 16;"
                 :: "r"(saddr), "l"(gptr));
}
__device__ __forceinline__ void cp_commit() {
    asm volatile("cp.async.commit_group;");
}
template <int N>
__device__ __forceinline__ void cp_wait() {
    asm volatile("cp.async.wait_group %0;" :: "n"(N));
}

// 2^t on the FMA pipe only.
__device__ __forceinline__ float exp2_poly(float t) {
    float g  = t + 12582912.0f;
    int   j  = __float_as_int(g);
    float nf = g - 12582912.0f;
    float f  = t - nf;
    float p  = 0.0096181f;
    p = fmaf(p, f, 0.0555041f);
    p = fmaf(p, f, 0.2402265f);
    p = fmaf(p, f, 0.6931472f);
    p = fmaf(p, f, 1.0f);
    int n = j - 0x4B400000;
    return __int_as_float(__float_as_int(p) + (n << 23));
}

// ---------------------------------------------------------------------------
// Elementwise f32 -> fp16 (rn) pre-convert pass. 8 elems/iter.
// ---------------------------------------------------------------------------
__global__ void cvt_f16_kernel(const float* __restrict__ in,
                               __half* __restrict__ out, int n8)
{
    int i = blockIdx.x * blockDim.x + threadIdx.x;
    int step = gridDim.x * blockDim.x;
    for (; i < n8; i += step) {
        float4 v0 = *(const float4*)(in + (size_t)i * 8);
        float4 v1 = *(const float4*)(in + (size_t)i * 8 + 4);
        __half2 h0 = __floats2half2_rn(v0.x, v0.y);
        __half2 h1 = __floats2half2_rn(v0.z, v0.w);
        __half2 h2 = __floats2half2_rn(v1.x, v1.y);
        __half2 h3 = __floats2half2_rn(v1.z, v1.w);
        uint4 o;
        o.x = *(uint32_t*)&h0; o.y = *(uint32_t*)&h1;
        o.z = *(uint32_t*)&h2; o.w = *(uint32_t*)&h3;
        *(uint4*)(out + (size_t)i * 8) = o;
    }
}

// ---------------------------------------------------------------------------
// FP16 tensor-core GEMM: 4-stage cp.async pipeline + ldmatrix fragment feed.
// C[M,N] = A[M,K] @ B[N,K]^T + bias[N]
// BM=BN=128, BK=32 halfs. 256 threads = 8 warps (2x4), warp tile 64x32.
// ---------------------------------------------------------------------------
#define BM 128
#define BN 128
#define BKH 32
#define LDW 20
#define STAGES 4
#define A_WORDS (BM * LDW)
#define STG_WORDS ((BM + BN) * LDW)
#define GEMM_SMEM_BYTES (STAGES * STG_WORDS * 4)   // 81920

template <bool HOUT>
__global__ __launch_bounds__(256) void gemm_f16_kernel(
    const __half* __restrict__ A, const __half* __restrict__ Bw,
    const float* __restrict__ bias, void* __restrict__ Cv,
    int M, int N, int K)
{
    extern __shared__ uint32_t gsm[];

    const int tid  = threadIdx.x;
    const int lane = tid & 31;
    const int warp = tid >> 5;
    const int wm   = warp >> 2;
    const int wn   = warp & 3;
    const int m0   = blockIdx.y * BM;
    const int n0   = blockIdx.x * BN;

    const int lrow = tid >> 2;
    const int lq   = tid & 3;

    const __half* Aptr = A  + (size_t)(m0 + lrow) * K + lq * 8;
    const __half* Bptr = Bw + (size_t)(n0 + lrow) * K + lq * 8;

    const uint32_t smem_base = (uint32_t)__cvta_generic_to_shared(gsm);
    const uint32_t a_off0 = ((lrow)      * LDW + lq * 4) * 4;
    const uint32_t a_off1 = ((lrow + 64) * LDW + lq * 4) * 4;
    const uint32_t b_off0 = (A_WORDS + (lrow)      * LDW + lq * 4) * 4;
    const uint32_t b_off1 = (A_WORDS + (lrow + 64) * LDW + lq * 4) * 4;

    // ldmatrix lane addressing
    const int a_lr = (lane & 7) + ((lane >> 3) & 1) * 8;
    const int a_lk = ((lane >> 4) & 1) * 4;
    const int b_lr = (lane & 7) + ((lane >> 4) & 1) * 8;
    const int b_lk = ((lane >> 3) & 1) * 4;

    const int nk = K / BKH;

    float acc[4][4][4];
    #pragma unroll
    for (int mi = 0; mi < 4; mi++)
        #pragma unroll
        for (int ni = 0; ni < 4; ni++)
            #pragma unroll
            for (int r = 0; r < 4; r++) acc[mi][ni][r] = 0.0f;

    #pragma unroll
    for (int s = 0; s < STAGES - 1; s++) {
        uint32_t sb = smem_base + s * STG_WORDS * 4;
        const __half* Ak = Aptr + (size_t)s * BKH;
        const __half* Bk = Bptr + (size_t)s * BKH;
        cp_async16(sb + a_off0, Ak);
        cp_async16(sb + a_off1, Ak + (size_t)64 * K);
        cp_async16(sb + b_off0, Bk);
        cp_async16(sb + b_off1, Bk + (size_t)64 * K);
        cp_commit();
    }

    const int qr = lane >> 2;
    const int qc = lane & 3;

    for (int kt = 0; kt < nk; kt++) {
        cp_wait<STAGES - 2>();
        __syncthreads();

        if (kt + STAGES - 1 < nk) {
            int s = (kt + STAGES - 1) & (STAGES - 1);
            uint32_t sb = smem_base + s * STG_WORDS * 4;
            const __half* Ak = Aptr + (size_t)(kt + STAGES - 1) * BKH;
            const __half* Bk = Bptr + (size_t)(kt + STAGES - 1) * BKH;
            cp_async16(sb + a_off0, Ak);
            cp_async16(sb + a_off1, Ak + (size_t)64 * K);
            cp_async16(sb + b_off0, Bk);
            cp_async16(sb + b_off1, Bk + (size_t)64 * K);
        }
        cp_commit();

        const uint32_t stg = smem_base + (kt & (STAGES - 1)) * STG_WORDS * 4;

        #pragma unroll
        for (int ks = 0; ks < 2; ks++) {
            const int kb = ks * 8;
            uint32_t afr[4][4];
            #pragma unroll
            for (int mi = 0; mi < 4; mi++)
                ldsm_x4(afr[mi],
                        stg + ((wm * 64 + mi * 16 + a_lr) * LDW + kb + a_lk) * 4);
            uint32_t bfr[2][4];
            #pragma unroll
            for (int p = 0; p < 2; p++)
                ldsm_x4(bfr[p],
                        stg + (A_WORDS + (wn * 32 + p * 16 + b_lr) * LDW + kb + b_lk) * 4);
            #pragma unroll
            for (int mi = 0; mi < 4; mi++)
                #pragma unroll
                for (int p = 0; p < 2; p++) {
                    mma_f16(acc[mi][2 * p],     afr[mi], &bfr[p][0]);
                    mma_f16(acc[mi][2 * p + 1], afr[mi], &bfr[p][2]);
                }
        }
    }

    // Epilogue
    #pragma unroll
    for (int ni = 0; ni < 4; ni++) {
        int col = n0 + wn * 32 + ni * 8 + qc * 2;
        float2 bv = *(const float2*)(bias + col);
        float scl = 1.0f;
        if (HOUT && col < D_) scl = QSC;   // q-block pre-scale (log2 domain)
        #pragma unroll
        for (int mi = 0; mi < 4; mi++) {
            int row = m0 + wm * 64 + mi * 16 + qr;
            float o00 = (acc[mi][ni][0] + bv.x) * scl;
            float o01 = (acc[mi][ni][1] + bv.y) * scl;
            float o10 = (acc[mi][ni][2] + bv.x) * scl;
            float o11 = (acc[mi][ni][3] + bv.y) * scl;
            if (HOUT) {
                __half* Ch = (__half*)Cv;
                *(__half2*)(Ch + (size_t)row * N + col) =
                    __floats2half2_rn(o00, o01);
                *(__half2*)(Ch + (size_t)(row + 8) * N + col) =
                    __floats2half2_rn(o10, o11);
            } else {
                float* Cf = (float*)Cv;
                *(float2*)(Cf + (size_t)row * N + col) = make_float2(o00, o01);
                *(float2*)(Cf + (size_t)(row + 8) * N + col) = make_float2(o10, o11);
            }
        }
    }
}

// ---------------------------------------------------------------------------
// FP16 flash attention, 128-row Q tiles (8 warps), ldmatrix feed,
// trans-ldmatrix V. Block = (b, h, 128-row q tile); 256 threads.
// smem (words, stride AST=36): Qs[128], Ks[64], Ps[128], Vs[64]
// ---------------------------------------------------------------------------
#define AST 36
#define AT_ROWS (128 + 64 + 128 + 64)
#define AT_BYTES (AT_ROWS * AST * 4)    // 55296

__global__ __launch_bounds__(256) void attn_f16_kernel(
    const __half* __restrict__ qkv, __half* __restrict__ out)
{
    const int bid = blockIdx.x;
    const int qt  = bid & 3;             // 4 q-tiles of 128
    const int h   = (bid >> 2) % H_;
    const int b   = bid / (H_ * 4);

    const int tid  = threadIdx.x;
    const int lane = tid & 31;
    const int warp = tid >> 5;           // 0..7
    const int qr   = lane >> 2;
    const int qc   = lane & 3;
    const int R    = warp * 16;          // 0..112

    extern __shared__ uint32_t smu[];
    uint32_t* Qs = smu;                   // [128][AST]
    uint32_t* Ks = smu + 128 * AST;       // [64][AST]
    uint32_t* Ps = smu + 192 * AST;       // [128][AST]
    uint32_t* Vs = smu + 320 * AST;       // [64][AST]

    const uint32_t sb  = (uint32_t)__cvta_generic_to_shared(smu);
    const uint32_t Qb  = sb;
    const uint32_t Kb  = sb + 128 * AST * 4;
    const uint32_t Pb  = sb + 192 * AST * 4;
    const uint32_t Vb  = sb + 320 * AST * 4;

    // ldmatrix lane addressing
    const int a_lr = (lane & 7) + ((lane >> 3) & 1) * 8;
    const int a_lk = ((lane >> 4) & 1) * 4;
    const int b_lr = (lane & 7) + ((lane >> 4) & 1) * 8;
    const int b_lk = ((lane >> 3) & 1) * 4;
    const int v_lk = (lane & 7) + ((lane >> 3) & 1) * 8;
    const int v_ld = ((lane >> 4) & 1) * 4;

    const __half* qbase = qkv + (size_t)(b * S_ + qt * 128) * QKV_N + h * HD_;

    // Load Q tile (already QSC-scaled): 128 rows x 64 halves
    for (int t = tid; t < 1024; t += 256) {
        int r = t >> 3;
        int c = t & 7;
        uint4 v = *(const uint4*)(qbase + (size_t)r * QKV_N + c * 8);
        *(uint4*)&Qs[r * AST + c * 4] = v;
    }

    float m1 = -1e30f, m2 = -1e30f, l1 = 0.0f, l2 = 0.0f;
    float o[8][4];
    #pragma unroll
    for (int nt = 0; nt < 8; nt++)
        #pragma unroll
        for (int r = 0; r < 4; r++) o[nt][r] = 0.0f;

    for (int kt = 0; kt < 8; kt++) {
        const __half* kbase = qkv + (size_t)(b * S_ + kt * 64) * QKV_N + D_ + h * HD_;
        const __half* vbase = kbase + D_;

        __syncthreads();   // prior tile reads done
        for (int t = tid; t < 512; t += 256) {
            int r = t >> 3;
            int c = t & 7;
            uint4 kk = *(const uint4*)(kbase + (size_t)r * QKV_N + c * 8);
            *(uint4*)&Ks[r * AST + c * 4] = kk;
            uint4 vv = *(const uint4*)(vbase + (size_t)r * QKV_N + c * 8);
            *(uint4*)&Vs[r * AST + c * 4] = vv;
        }
        __syncthreads();

        // S = Q K^T  (log2 domain)
        float s[8][4];
        #pragma unroll
        for (int nt = 0; nt < 8; nt++)
            #pragma unroll
            for (int r = 0; r < 4; r++) s[nt][r] = 0.0f;

        #pragma unroll
        for (int ks = 0; ks < 4; ks++) {
            const int kb = ks * 8;
            uint32_t a[4];
            ldsm_x4(a, Qb + ((R + a_lr) * AST + kb + a_lk) * 4);
            #pragma unroll
            for (int p = 0; p < 4; p++) {
                uint32_t bb[4];
                ldsm_x4(bb, Kb + ((p * 16 + b_lr) * AST + kb + b_lk) * 4);
                mma_f16(s[2 * p],     a, &bb[0]);
                mma_f16(s[2 * p + 1], a, &bb[2]);
            }
        }

        // Online softmax (base-2)
        float mx1 = -1e30f, mx2 = -1e30f;
        #pragma unroll
        for (int nt = 0; nt < 8; nt++) {
            mx1 = fmaxf(mx1, fmaxf(s[nt][0], s[nt][1]));
            mx2 = fmaxf(mx2, fmaxf(s[nt][2], s[nt][3]));
        }
        mx1 = fmaxf(mx1, __shfl_xor_sync(0xffffffffu, mx1, 1));
        mx1 = fmaxf(mx1, __shfl_xor_sync(0xffffffffu, mx1, 2));
        mx2 = fmaxf(mx2, __shfl_xor_sync(0xffffffffu, mx2, 1));
        mx2 = fmaxf(mx2, __shfl_xor_sync(0xffffffffu, mx2, 2));

        float mn1 = fmaxf(m1, mx1);
        float mn2 = fmaxf(m2, mx2);
        float c1 = exp2f(m1 - mn1);
        float c2 = exp2f(m2 - mn2);
        m1 = mn1; m2 = mn2;

        float rs1 = 0.0f, rs2 = 0.0f;
        #pragma unroll
        for (int nt = 0; nt < 8; nt++) {
            s[nt][0] = exp2_poly(s[nt][0] - mn1);
            s[nt][1] = exp2_poly(s[nt][1] - mn1);
            s[nt][2] = exp2_poly(s[nt][2] - mn2);
            s[nt][3] = exp2_poly(s[nt][3] - mn2);
            rs1 += s[nt][0] + s[nt][1];
            rs2 += s[nt][2] + s[nt][3];
        }
        rs1 += __shfl_xor_sync(0xffffffffu, rs1, 1);
        rs1 += __shfl_xor_sync(0xffffffffu, rs1, 2);
        rs2 += __shfl_xor_sync(0xffffffffu, rs2, 1);
        rs2 += __shfl_xor_sync(0xffffffffu, rs2, 2);
        l1 = l1 * c1 + rs1;
        l2 = l2 * c2 + rs2;

        #pragma unroll
        for (int nt = 0; nt < 8; nt++) {
            o[nt][0] *= c1; o[nt][1] *= c1;
            o[nt][2] *= c2; o[nt][3] *= c2;
        }

        // Stage P (fp16): word (nt*4 + qc) = cols nt*8 + 2qc, +1
        #pragma unroll
        for (int nt = 0; nt < 8; nt++) {
            __half2 p0 = __floats2half2_rn(s[nt][0], s[nt][1]);
            __half2 p1 = __floats2half2_rn(s[nt][2], s[nt][3]);
            Ps[(R + qr) * AST + nt * 4 + qc]     = *(uint32_t*)&p0;
            Ps[(R + qr + 8) * AST + nt * 4 + qc] = *(uint32_t*)&p1;
        }
        __syncwarp();

        // O += P @ V  (A = P rows via ldmatrix; B = V via trans-ldmatrix)
        #pragma unroll
        for (int ks = 0; ks < 4; ks++) {
            const int kb = ks * 8;
            uint32_t a[4];
            ldsm_x4(a, Pb + ((R + a_lr) * AST + kb + a_lk) * 4);
            #pragma unroll
            for (int p = 0; p < 4; p++) {
                uint32_t bb[4];
                ldsm_x4_trans(bb, Vb + ((ks * 16 + v_lk) * AST + p * 8 + v_ld) * 4);
                mma_f16(o[2 * p],     a, &bb[0]);
                mma_f16(o[2 * p + 1], a, &bb[2]);
            }
        }
        __syncwarp();
    }

    // Normalize + store fp16 (consumed only by proj GEMM)
    float i1 = 1.0f / l1;
    float i2 = 1.0f / l2;
    __half* ob = out + (size_t)(b * S_ + qt * 128) * D_ + h * HD_;
    #pragma unroll
    for (int nt = 0; nt < 8; nt++) {
        int col = nt * 8 + 2 * qc;
        __half2 w0 = __floats2half2_rn(o[nt][0] * i1, o[nt][1] * i1);
        __half2 w1 = __floats2half2_rn(o[nt][2] * i2, o[nt][3] * i2);
        *(__half2*)(ob + (size_t)(R + qr) * D_ + col)     = w0;
        *(__half2*)(ob + (size_t)(R + qr + 8) * D_ + col) = w1;
    }
}

// ---------------------------------------------------------------------------
// Launch
// ---------------------------------------------------------------------------
extern "C" void kernel_launch(void* const* d_in, const int* in_sizes, int n_in,
                              void* d_out, int out_size)
{
    const float* x      = (const float*)d_in[0];
    const float* qkv_w  = (const float*)d_in[1];
    const float* qkv_b  = (const float*)d_in[2];
    const float* proj_w = (const float*)d_in[3];
    const float* proj_b = (const float*)d_in[4];
    float* out = (float*)d_out;

    void *qkvh_p, *attnh_p, *xh_p, *qkvwh_p, *projwh_p;
    cudaGetSymbolAddress(&qkvh_p, g_qkvh);
    cudaGetSymbolAddress(&attnh_p, g_attnh);
    cudaGetSymbolAddress(&xh_p, g_xh);
    cudaGetSymbolAddress(&qkvwh_p, g_qkvwh);
    cudaGetSymbolAddress(&projwh_p, g_projwh);
    __half* qkvh_s   = (__half*)qkvh_p;
    __half* attnh_s  = (__half*)attnh_p;
    __half* xh_s     = (__half*)xh_p;
    __half* qkvwh_s  = (__half*)qkvwh_p;
    __half* projwh_s = (__half*)projwh_p;

    cudaFuncSetAttribute(gemm_f16_kernel<true>,
                         cudaFuncAttributeMaxDynamicSharedMemorySize,
                         GEMM_SMEM_BYTES);
    cudaFuncSetAttribute(gemm_f16_kernel<false>,
                         cudaFuncAttributeMaxDynamicSharedMemorySize,
                         GEMM_SMEM_BYTES);
    cudaFuncSetAttribute(attn_f16_kernel,
                         cudaFuncAttributeMaxDynamicSharedMemorySize,
                         AT_BYTES);

    // 0) Pre-convert inputs to fp16 (rn)
    cvt_f16_kernel<<<1024, 256>>>(x, xh_s, M_TOT * D_ / 8);
    cvt_f16_kernel<<<512, 256>>>(qkv_w, qkvwh_s, QKV_N * D_ / 8);
    cvt_f16_kernel<<<256, 256>>>(proj_w, projwh_s, D_ * D_ / 8);

    // 1) QKV projection -> fp16 qkv (q cols pre-scaled by QSC)
    gemm_f16_kernel<true><<<dim3(QKV_N / BN, M_TOT / BM), 256, GEMM_SMEM_BYTES>>>(
        xh_s, qkvwh_s, qkv_b, qkvh_s, M_TOT, QKV_N, D_);

    // 2) Flash attention (128-row Q tiles)
    attn_f16_kernel<<<B_ * H_ * (S_ / 128), 256, AT_BYTES>>>(qkvh_s, attnh_s);

    // 3) Output projection -> f32 out
    gemm_f16_kernel<false><<<dim3(D_ / BN, M_TOT / BM), 256, GEMM_SMEM_BYTES>>>(
        attnh_s, projwh_s, proj_b, out, M_TOT, D_, D_);
}

// round 15
// speedup vs baseline: 2.9201x; 1.0823x over previous
#include <cuda_runtime.h>
#include <cuda_fp16.h>
#include <cstdint>

// Problem constants
#define B_  32
#define S_  512
#define D_  768
#define H_  12
#define HD_ 64
#define SCALE_ 0.125f
// SCALE * log2(e): scores computed directly in log2 domain
#define QSC 0.18033688011112042f

#define M_TOT (B_ * S_)          // 16384
#define QKV_N (3 * D_)           // 2304

// Scratch (device globals — allocation-free)
__device__ __half g_qkvh[(size_t)M_TOT * QKV_N];   // [M, 3D] fp16 QKV (q pre-scaled)
__device__ __half g_attnh[(size_t)M_TOT * D_];     // [M, D] attn out (fp16)
__device__ __half g_xh[(size_t)M_TOT * D_];        // x as fp16
__device__ __half g_qkvwh[(size_t)QKV_N * D_];     // qkv_w as fp16
__device__ __half g_projwh[(size_t)D_ * D_];       // proj_w as fp16

// ---------------------------------------------------------------------------
// Helpers
// ---------------------------------------------------------------------------
__device__ __forceinline__ void mma_f16(float d[4], const uint32_t a[4],
                                        const uint32_t b[2]) {
    asm volatile(
        "mma.sync.aligned.m16n8k16.row.col.f32.f16.f16.f32 "
        "{%0,%1,%2,%3},{%4,%5,%6,%7},{%8,%9},{%0,%1,%2,%3};\n"
        : "+f"(d[0]), "+f"(d[1]), "+f"(d[2]), "+f"(d[3])
        : "r"(a[0]), "r"(a[1]), "r"(a[2]), "r"(a[3]),
          "r"(b[0]), "r"(b[1]));
}

__device__ __forceinline__ void ldsm_x4(uint32_t r[4], uint32_t saddr) {
    asm volatile(
        "ldmatrix.sync.aligned.m8n8.x4.shared.b16 {%0,%1,%2,%3},[%4];"
        : "=r"(r[0]), "=r"(r[1]), "=r"(r[2]), "=r"(r[3]) : "r"(saddr));
}
__device__ __forceinline__ void ldsm_x4_trans(uint32_t r[4], uint32_t saddr) {
    asm volatile(
        "ldmatrix.sync.aligned.m8n8.x4.trans.shared.b16 {%0,%1,%2,%3},[%4];"
        : "=r"(r[0]), "=r"(r[1]), "=r"(r[2]), "=r"(r[3]) : "r"(saddr));
}

__device__ __forceinline__ void cp_async16(uint32_t saddr, const void* gptr) {
    asm volatile("cp.async.cg.shared.global [%0], [%1], 16;"
                 :: "r"(saddr), "l"(gptr));
}
__device__ __forceinline__ void cp_commit() {
    asm volatile("cp.async.commit_group;");
}
template <int N>
__device__ __forceinline__ void cp_wait() {
    asm volatile("cp.async.wait_group %0;" :: "n"(N));
}

// 2^t on the FMA pipe only.
__device__ __forceinline__ float exp2_poly(float t) {
    float g  = t + 12582912.0f;
    int   j  = __float_as_int(g);
    float nf = g - 12582912.0f;
    float f  = t - nf;
    float p  = 0.0096181f;
    p = fmaf(p, f, 0.0555041f);
    p = fmaf(p, f, 0.2402265f);
    p = fmaf(p, f, 0.6931472f);
    p = fmaf(p, f, 1.0f);
    int n = j - 0x4B400000;
    return __int_as_float(__float_as_int(p) + (n << 23));
}

// ---------------------------------------------------------------------------
// Elementwise f32 -> fp16 (rn) pre-convert pass. 8 elems/iter.
// ---------------------------------------------------------------------------
__global__ void cvt_f16_kernel(const float* __restrict__ in,
                               __half* __restrict__ out, int n8)
{
    int i = blockIdx.x * blockDim.x + threadIdx.x;
    int step = gridDim.x * blockDim.x;
    for (; i < n8; i += step) {
        float4 v0 = *(const float4*)(in + (size_t)i * 8);
        float4 v1 = *(const float4*)(in + (size_t)i * 8 + 4);
        __half2 h0 = __floats2half2_rn(v0.x, v0.y);
        __half2 h1 = __floats2half2_rn(v0.z, v0.w);
        __half2 h2 = __floats2half2_rn(v1.x, v1.y);
        __half2 h3 = __floats2half2_rn(v1.z, v1.w);
        uint4 o;
        o.x = *(uint32_t*)&h0; o.y = *(uint32_t*)&h1;
        o.z = *(uint32_t*)&h2; o.w = *(uint32_t*)&h3;
        *(uint4*)(out + (size_t)i * 8) = o;
    }
}

// ---------------------------------------------------------------------------
// FP16 tensor-core GEMM: 4-stage cp.async pipeline + ldmatrix fragment feed.
// C[M,N] = A[M,K] @ B[N,K]^T + bias[N]
// BM=BN=128, BK=32 halfs. 256 threads = 8 warps (2x4), warp tile 64x32.
// ---------------------------------------------------------------------------
#define BM 128
#define BN 128
#define BKH 32
#define LDW 20
#define STAGES 4
#define A_WORDS (BM * LDW)
#define STG_WORDS ((BM + BN) * LDW)
#define GEMM_SMEM_BYTES (STAGES * STG_WORDS * 4)   // 81920

template <bool HOUT>
__global__ __launch_bounds__(256) void gemm_f16_kernel(
    const __half* __restrict__ A, const __half* __restrict__ Bw,
    const float* __restrict__ bias, void* __restrict__ Cv,
    int M, int N, int K)
{
    extern __shared__ uint32_t gsm[];

    const int tid  = threadIdx.x;
    const int lane = tid & 31;
    const int warp = tid >> 5;
    const int wm   = warp >> 2;
    const int wn   = warp & 3;
    const int m0   = blockIdx.y * BM;
    const int n0   = blockIdx.x * BN;

    const int lrow = tid >> 2;
    const int lq   = tid & 3;

    const __half* Aptr = A  + (size_t)(m0 + lrow) * K + lq * 8;
    const __half* Bptr = Bw + (size_t)(n0 + lrow) * K + lq * 8;

    const uint32_t smem_base = (uint32_t)__cvta_generic_to_shared(gsm);
    const uint32_t a_off0 = ((lrow)      * LDW + lq * 4) * 4;
    const uint32_t a_off1 = ((lrow + 64) * LDW + lq * 4) * 4;
    const uint32_t b_off0 = (A_WORDS + (lrow)      * LDW + lq * 4) * 4;
    const uint32_t b_off1 = (A_WORDS + (lrow + 64) * LDW + lq * 4) * 4;

    // ldmatrix lane addressing
    const int a_lr = (lane & 7) + ((lane >> 3) & 1) * 8;
    const int a_lk = ((lane >> 4) & 1) * 4;
    const int b_lr = (lane & 7) + ((lane >> 4) & 1) * 8;
    const int b_lk = ((lane >> 3) & 1) * 4;

    const int nk = K / BKH;

    float acc[4][4][4];
    #pragma unroll
    for (int mi = 0; mi < 4; mi++)
        #pragma unroll
        for (int ni = 0; ni < 4; ni++)
            #pragma unroll
            for (int r = 0; r < 4; r++) acc[mi][ni][r] = 0.0f;

    #pragma unroll
    for (int s = 0; s < STAGES - 1; s++) {
        uint32_t sb = smem_base + s * STG_WORDS * 4;
        const __half* Ak = Aptr + (size_t)s * BKH;
        const __half* Bk = Bptr + (size_t)s * BKH;
        cp_async16(sb + a_off0, Ak);
        cp_async16(sb + a_off1, Ak + (size_t)64 * K);
        cp_async16(sb + b_off0, Bk);
        cp_async16(sb + b_off1, Bk + (size_t)64 * K);
        cp_commit();
    }

    const int qr = lane >> 2;
    const int qc = lane & 3;

    for (int kt = 0; kt < nk; kt++) {
        cp_wait<STAGES - 2>();
        __syncthreads();

        if (kt + STAGES - 1 < nk) {
            int s = (kt + STAGES - 1) & (STAGES - 1);
            uint32_t sb = smem_base + s * STG_WORDS * 4;
            const __half* Ak = Aptr + (size_t)(kt + STAGES - 1) * BKH;
            const __half* Bk = Bptr + (size_t)(kt + STAGES - 1) * BKH;
            cp_async16(sb + a_off0, Ak);
            cp_async16(sb + a_off1, Ak + (size_t)64 * K);
            cp_async16(sb + b_off0, Bk);
            cp_async16(sb + b_off1, Bk + (size_t)64 * K);
        }
        cp_commit();

        const uint32_t stg = smem_base + (kt & (STAGES - 1)) * STG_WORDS * 4;

        #pragma unroll
        for (int ks = 0; ks < 2; ks++) {
            const int kb = ks * 8;
            uint32_t afr[4][4];
            #pragma unroll
            for (int mi = 0; mi < 4; mi++)
                ldsm_x4(afr[mi],
                        stg + ((wm * 64 + mi * 16 + a_lr) * LDW + kb + a_lk) * 4);
            uint32_t bfr[2][4];
            #pragma unroll
            for (int p = 0; p < 2; p++)
                ldsm_x4(bfr[p],
                        stg + (A_WORDS + (wn * 32 + p * 16 + b_lr) * LDW + kb + b_lk) * 4);
            #pragma unroll
            for (int mi = 0; mi < 4; mi++)
                #pragma unroll
                for (int p = 0; p < 2; p++) {
                    mma_f16(acc[mi][2 * p],     afr[mi], &bfr[p][0]);
                    mma_f16(acc[mi][2 * p + 1], afr[mi], &bfr[p][2]);
                }
        }
    }

    // Epilogue
    #pragma unroll
    for (int ni = 0; ni < 4; ni++) {
        int col = n0 + wn * 32 + ni * 8 + qc * 2;
        float2 bv = *(const float2*)(bias + col);
        float scl = 1.0f;
        if (HOUT && col < D_) scl = QSC;   // q-block pre-scale (log2 domain)
        #pragma unroll
        for (int mi = 0; mi < 4; mi++) {
            int row = m0 + wm * 64 + mi * 16 + qr;
            float o00 = (acc[mi][ni][0] + bv.x) * scl;
            float o01 = (acc[mi][ni][1] + bv.y) * scl;
            float o10 = (acc[mi][ni][2] + bv.x) * scl;
            float o11 = (acc[mi][ni][3] + bv.y) * scl;
            if (HOUT) {
                __half* Ch = (__half*)Cv;
                *(__half2*)(Ch + (size_t)row * N + col) =
                    __floats2half2_rn(o00, o01);
                *(__half2*)(Ch + (size_t)(row + 8) * N + col) =
                    __floats2half2_rn(o10, o11);
            } else {
                float* Cf = (float*)Cv;
                *(float2*)(Cf + (size_t)row * N + col) = make_float2(o00, o01);
                *(float2*)(Cf + (size_t)(row + 8) * N + col) = make_float2(o10, o11);
            }
        }
    }
}

// ---------------------------------------------------------------------------
// FP16 flash attention: 128-row Q tiles, 3-stage cp.async K/V ring,
// ldmatrix fragment feed, trans-ldmatrix V.
// Block = (b, h, 128-row q tile); 256 threads = 8 warps, warp owns 16 q rows.
// smem (words, stride AST=36): Qs[128], Ps[128], 3x(K[64]+V[64])
// ---------------------------------------------------------------------------
#define AST 36
#define Q_WORDS (128 * AST)            // 4608
#define KV_STG_WORDS (128 * AST)       // 4608 (K 64 rows + V 64 rows)
#define AT_WORDS (2 * Q_WORDS + 3 * KV_STG_WORDS)
#define AT_BYTES (AT_WORDS * 4)        // 92160

__global__ __launch_bounds__(256) void attn_f16_kernel(
    const __half* __restrict__ qkv, __half* __restrict__ out)
{
    const int bid = blockIdx.x;
    const int qt  = bid & 3;             // 4 q-tiles of 128
    const int h   = (bid >> 2) % H_;
    const int b   = bid / (H_ * 4);

    const int tid  = threadIdx.x;
    const int lane = tid & 31;
    const int warp = tid >> 5;           // 0..7
    const int qr   = lane >> 2;
    const int qc   = lane & 3;
    const int R    = warp * 16;          // 0..112

    extern __shared__ uint32_t smu[];
    uint32_t* Ps = smu + Q_WORDS;        // [128][AST]

    const uint32_t sb = (uint32_t)__cvta_generic_to_shared(smu);
    const uint32_t Qb = sb;
    const uint32_t Pb = sb + Q_WORDS * 4;
    const uint32_t KVb = sb + 2 * Q_WORDS * 4;   // stage s at KVb + s*KV_STG_WORDS*4

    // ldmatrix lane addressing
    const int a_lr = (lane & 7) + ((lane >> 3) & 1) * 8;
    const int a_lk = ((lane >> 4) & 1) * 4;
    const int b_lr = (lane & 7) + ((lane >> 4) & 1) * 8;
    const int b_lk = ((lane >> 3) & 1) * 4;
    const int v_lk = (lane & 7) + ((lane >> 3) & 1) * 8;
    const int v_ld = ((lane >> 4) & 1) * 4;

    // K/V loader mapping: 2 iters x 256 threads cover 64 rows x 8 chunks
    const int krow0 = tid >> 3;          // 0..31
    const int krow1 = krow0 + 32;
    const int kc    = tid & 7;

    const __half* kv_base = qkv + (size_t)(b * S_) * QKV_N + D_ + h * HD_;

    // Prologue: issue K/V tiles 0, 1
    #pragma unroll
    for (int s = 0; s < 2; s++) {
        uint32_t stg = KVb + s * KV_STG_WORDS * 4;
        const __half* kb = kv_base + (size_t)(s * 64) * QKV_N;
        cp_async16(stg + (krow0 * AST + kc * 4) * 4, kb + (size_t)krow0 * QKV_N + kc * 8);
        cp_async16(stg + (krow1 * AST + kc * 4) * 4, kb + (size_t)krow1 * QKV_N + kc * 8);
        cp_async16(stg + ((64 + krow0) * AST + kc * 4) * 4, kb + (size_t)krow0 * QKV_N + D_ + kc * 8);
        cp_async16(stg + ((64 + krow1) * AST + kc * 4) * 4, kb + (size_t)krow1 * QKV_N + D_ + kc * 8);
        cp_commit();
    }

    // Q tile load (already QSC-scaled): overlaps with in-flight cp.asyncs
    const __half* qbase = qkv + (size_t)(b * S_ + qt * 128) * QKV_N + h * HD_;
    for (int t = tid; t < 1024; t += 256) {
        int r = t >> 3;
        int c = t & 7;
        uint4 v = *(const uint4*)(qbase + (size_t)r * QKV_N + c * 8);
        *(uint4*)&smu[r * AST + c * 4] = v;
    }

    float m1 = -1e30f, m2 = -1e30f, l1 = 0.0f, l2 = 0.0f;
    float o[8][4];
    #pragma unroll
    for (int nt = 0; nt < 8; nt++)
        #pragma unroll
        for (int r = 0; r < 4; r++) o[nt][r] = 0.0f;

    int stage = 0;
    for (int kt = 0; kt < 8; kt++) {
        cp_wait<1>();        // tile kt complete (tile kt+1 may be in flight)
        __syncthreads();     // everyone sees it; everyone done computing kt-1

        // Issue tile kt+2 into stage (kt+2)%3 (== (kt-1)%3, safe after sync)
        if (kt + 2 < 8) {
            int s2 = stage + 2; if (s2 >= 3) s2 -= 3;
            uint32_t stg = KVb + s2 * KV_STG_WORDS * 4;
            const __half* kb = kv_base + (size_t)((kt + 2) * 64) * QKV_N;
            cp_async16(stg + (krow0 * AST + kc * 4) * 4, kb + (size_t)krow0 * QKV_N + kc * 8);
            cp_async16(stg + (krow1 * AST + kc * 4) * 4, kb + (size_t)krow1 * QKV_N + kc * 8);
            cp_async16(stg + ((64 + krow0) * AST + kc * 4) * 4, kb + (size_t)krow0 * QKV_N + D_ + kc * 8);
            cp_async16(stg + ((64 + krow1) * AST + kc * 4) * 4, kb + (size_t)krow1 * QKV_N + D_ + kc * 8);
        }
        cp_commit();

        const uint32_t Kb = KVb + stage * KV_STG_WORDS * 4;
        const uint32_t Vb = Kb + 64 * AST * 4;

        // S = Q K^T  (log2 domain)
        float s[8][4];
        #pragma unroll
        for (int nt = 0; nt < 8; nt++)
            #pragma unroll
            for (int r = 0; r < 4; r++) s[nt][r] = 0.0f;

        #pragma unroll
        for (int ks = 0; ks < 4; ks++) {
            const int kb = ks * 8;
            uint32_t a[4];
            ldsm_x4(a, Qb + ((R + a_lr) * AST + kb + a_lk) * 4);
            #pragma unroll
            for (int p = 0; p < 4; p++) {
                uint32_t bb[4];
                ldsm_x4(bb, Kb + ((p * 16 + b_lr) * AST + kb + b_lk) * 4);
                mma_f16(s[2 * p],     a, &bb[0]);
                mma_f16(s[2 * p + 1], a, &bb[2]);
            }
        }

        // Online softmax (base-2)
        float mx1 = -1e30f, mx2 = -1e30f;
        #pragma unroll
        for (int nt = 0; nt < 8; nt++) {
            mx1 = fmaxf(mx1, fmaxf(s[nt][0], s[nt][1]));
            mx2 = fmaxf(mx2, fmaxf(s[nt][2], s[nt][3]));
        }
        mx1 = fmaxf(mx1, __shfl_xor_sync(0xffffffffu, mx1, 1));
        mx1 = fmaxf(mx1, __shfl_xor_sync(0xffffffffu, mx1, 2));
        mx2 = fmaxf(mx2, __shfl_xor_sync(0xffffffffu, mx2, 1));
        mx2 = fmaxf(mx2, __shfl_xor_sync(0xffffffffu, mx2, 2));

        float mn1 = fmaxf(m1, mx1);
        float mn2 = fmaxf(m2, mx2);
        float c1 = exp2f(m1 - mn1);
        float c2 = exp2f(m2 - mn2);
        m1 = mn1; m2 = mn2;

        float rs1 = 0.0f, rs2 = 0.0f;
        #pragma unroll
        for (int nt = 0; nt < 8; nt++) {
            s[nt][0] = exp2_poly(s[nt][0] - mn1);
            s[nt][1] = exp2_poly(s[nt][1] - mn1);
            s[nt][2] = exp2_poly(s[nt][2] - mn2);
            s[nt][3] = exp2_poly(s[nt][3] - mn2);
            rs1 += s[nt][0] + s[nt][1];
            rs2 += s[nt][2] + s[nt][3];
        }
        rs1 += __shfl_xor_sync(0xffffffffu, rs1, 1);
        rs1 += __shfl_xor_sync(0xffffffffu, rs1, 2);
        rs2 += __shfl_xor_sync(0xffffffffu, rs2, 1);
        rs2 += __shfl_xor_sync(0xffffffffu, rs2, 2);
        l1 = l1 * c1 + rs1;
        l2 = l2 * c2 + rs2;

        #pragma unroll
        for (int nt = 0; nt < 8; nt++) {
            o[nt][0] *= c1; o[nt][1] *= c1;
            o[nt][2] *= c2; o[nt][3] *= c2;
        }

        // Stage P (fp16): word (nt*4 + qc) = cols nt*8 + 2qc, +1
        #pragma unroll
        for (int nt = 0; nt < 8; nt++) {
            __half2 p0 = __floats2half2_rn(s[nt][0], s[nt][1]);
            __half2 p1 = __floats2half2_rn(s[nt][2], s[nt][3]);
            Ps[(R + qr) * AST + nt * 4 + qc]     = *(uint32_t*)&p0;
            Ps[(R + qr + 8) * AST + nt * 4 + qc] = *(uint32_t*)&p1;
        }
        __syncwarp();

        // O += P @ V  (A = P rows via ldmatrix; B = V via trans-ldmatrix)
        #pragma unroll
        for (int ks = 0; ks < 4; ks++) {
            const int kb = ks * 8;
            uint32_t a[4];
            ldsm_x4(a, Pb + ((R + a_lr) * AST + kb + a_lk) * 4);
            #pragma unroll
            for (int p = 0; p < 4; p++) {
                uint32_t bb[4];
                ldsm_x4_trans(bb, Vb + ((ks * 16 + v_lk) * AST + p * 8 + v_ld) * 4);
                mma_f16(o[2 * p],     a, &bb[0]);
                mma_f16(o[2 * p + 1], a, &bb[2]);
            }
        }
        __syncwarp();

        if (++stage == 3) stage = 0;
    }

    // Normalize + store fp16 (consumed only by proj GEMM)
    float i1 = 1.0f / l1;
    float i2 = 1.0f / l2;
    __half* ob = out + (size_t)(b * S_ + qt * 128) * D_ + h * HD_;
    #pragma unroll
    for (int nt = 0; nt < 8; nt++) {
        int col = nt * 8 + 2 * qc;
        __half2 w0 = __floats2half2_rn(o[nt][0] * i1, o[nt][1] * i1);
        __half2 w1 = __floats2half2_rn(o[nt][2] * i2, o[nt][3] * i2);
        *(__half2*)(ob + (size_t)(R + qr) * D_ + col)     = w0;
        *(__half2*)(ob + (size_t)(R + qr + 8) * D_ + col) = w1;
    }
}

// ---------------------------------------------------------------------------
// Launch
// ---------------------------------------------------------------------------
extern "C" void kernel_launch(void* const* d_in, const int* in_sizes, int n_in,
                              void* d_out, int out_size)
{
    const float* x      = (const float*)d_in[0];
    const float* qkv_w  = (const float*)d_in[1];
    const float* qkv_b  = (const float*)d_in[2];
    const float* proj_w = (const float*)d_in[3];
    const float* proj_b = (const float*)d_in[4];
    float* out = (float*)d_out;

    void *qkvh_p, *attnh_p, *xh_p, *qkvwh_p, *projwh_p;
    cudaGetSymbolAddress(&qkvh_p, g_qkvh);
    cudaGetSymbolAddress(&attnh_p, g_attnh);
    cudaGetSymbolAddress(&xh_p, g_xh);
    cudaGetSymbolAddress(&qkvwh_p, g_qkvwh);
    cudaGetSymbolAddress(&projwh_p, g_projwh);
    __half* qkvh_s   = (__half*)qkvh_p;
    __half* attnh_s  = (__half*)attnh_p;
    __half* xh_s     = (__half*)xh_p;
    __half* qkvwh_s  = (__half*)qkvwh_p;
    __half* projwh_s = (__half*)projwh_p;

    cudaFuncSetAttribute(gemm_f16_kernel<true>,
                         cudaFuncAttributeMaxDynamicSharedMemorySize,
                         GEMM_SMEM_BYTES);
    cudaFuncSetAttribute(gemm_f16_kernel<false>,
                         cudaFuncAttributeMaxDynamicSharedMemorySize,
                         GEMM_SMEM_BYTES);
    cudaFuncSetAttribute(attn_f16_kernel,
                         cudaFuncAttributeMaxDynamicSharedMemorySize,
                         AT_BYTES);

    // 0) Pre-convert inputs to fp16 (rn)
    cvt_f16_kernel<<<1024, 256>>>(x, xh_s, M_TOT * D_ / 8);
    cvt_f16_kernel<<<512, 256>>>(qkv_w, qkvwh_s, QKV_N * D_ / 8);
    cvt_f16_kernel<<<256, 256>>>(proj_w, projwh_s, D_ * D_ / 8);

    // 1) QKV projection -> fp16 qkv (q cols pre-scaled by QSC)
    gemm_f16_kernel<true><<<dim3(QKV_N / BN, M_TOT / BM), 256, GEMM_SMEM_BYTES>>>(
        xh_s, qkvwh_s, qkv_b, qkvh_s, M_TOT, QKV_N, D_);

    // 2) Flash attention (128-row Q tiles, cp.async K/V ring)
    attn_f16_kernel<<<B_ * H_ * (S_ / 128), 256, AT_BYTES>>>(qkvh_s, attnh_s);

    // 3) Output projection -> f32 out
    gemm_f16_kernel<false><<<dim3(D_ / BN, M_TOT / BM), 256, GEMM_SMEM_BYTES>>>(
        attnh_s, projwh_s, proj_b, out, M_TOT, D_, D_);
}